// round 1
// baseline (speedup 1.0000x reference)
#include <cuda_runtime.h>

#define NB 256
#define NP 512
#define NH 16
#define NK 8
#define NPTS (NB*NP)
#define PITCH4 5   // float4 per point row in shared (20 floats, conflict-spread, alignment kept)

__device__ float g_h [NPTS*NH];
__device__ float g_f1[NPTS*NH];
__device__ float g_f2[NPTS*NH];

__device__ __forceinline__ float elu1(float x) {
    return x > 0.f ? x : (__expf(x) - 1.f);
}

// ---------------------------------------------------------------- embed ----
__global__ void __launch_bounds__(256) k_embed(
    const float* __restrict__ x,
    const float* __restrict__ We1, const float* __restrict__ be1,
    const float* __restrict__ We2, const float* __restrict__ be2)
{
    int i = blockIdx.x * 256 + threadIdx.x;
    if (i >= NPTS) return;
    float4 xv = reinterpret_cast<const float4*>(x)[i];
    float t[NH];
#pragma unroll
    for (int c = 0; c < NH; c++) {
        float a = __ldg(&be1[c]);
        a = fmaf(xv.x, __ldg(&We1[0*NH+c]), a);
        a = fmaf(xv.y, __ldg(&We1[1*NH+c]), a);
        a = fmaf(xv.z, __ldg(&We1[2*NH+c]), a);
        a = fmaf(xv.w, __ldg(&We1[3*NH+c]), a);
        t[c] = elu1(a);
    }
    float4 o[4];
    float* op = reinterpret_cast<float*>(o);
#pragma unroll
    for (int c = 0; c < NH; c++) {
        float a = __ldg(&be2[c]);
#pragma unroll
        for (int d = 0; d < NH; d++) a = fmaf(t[d], __ldg(&We2[d*NH+c]), a);
        op[c] = elu1(a);
    }
    float4* dst = reinterpret_cast<float4*>(g_h + (size_t)i*NH);
    dst[0]=o[0]; dst[1]=o[1]; dst[2]=o[2]; dst[3]=o[3];
}

// ------------------------------------------------------------- edgeconv ----
// PHASE 0: g_h -> g_f1 ; PHASE 1: g_f1 -> g_f2
template<int PHASE>
__global__ void __launch_bounds__(256) k_edgeconv(
    const float* __restrict__ Wc, const float* __restrict__ bc)
{
    __shared__ float4 hsh[NP*PITCH4];
    __shared__ float  sqsh[NP];
    __shared__ float  w2t[NH*NH];   // [c][d] = Wc[(16+d)*16+c]
    __shared__ float  wdt[NH*NH];   // [c][d] = Wc[d*16+c] - w2
    __shared__ float  bcs[NH];

    const float* hin = (PHASE == 0) ? g_h  : g_f1;
    float*       fout= (PHASE == 0) ? g_f1 : g_f2;

    int tid = threadIdx.x;
    int b   = blockIdx.x >> 1;
    const float* hg = hin + (size_t)b*NP*NH;

    for (int r = tid; r < NP; r += 256) {
        const float4* src = reinterpret_cast<const float4*>(hg + r*NH);
        float4 v0=src[0], v1=src[1], v2=src[2], v3=src[3];
        hsh[r*PITCH4+0]=v0; hsh[r*PITCH4+1]=v1;
        hsh[r*PITCH4+2]=v2; hsh[r*PITCH4+3]=v3;
        float s = 0.f;
        s=fmaf(v0.x,v0.x,s); s=fmaf(v0.y,v0.y,s); s=fmaf(v0.z,v0.z,s); s=fmaf(v0.w,v0.w,s);
        s=fmaf(v1.x,v1.x,s); s=fmaf(v1.y,v1.y,s); s=fmaf(v1.z,v1.z,s); s=fmaf(v1.w,v1.w,s);
        s=fmaf(v2.x,v2.x,s); s=fmaf(v2.y,v2.y,s); s=fmaf(v2.z,v2.z,s); s=fmaf(v2.w,v2.w,s);
        s=fmaf(v3.x,v3.x,s); s=fmaf(v3.y,v3.y,s); s=fmaf(v3.z,v3.z,s); s=fmaf(v3.w,v3.w,s);
        sqsh[r] = s;
    }
    {   // W_c prep: transposed + xi/xj regroup
        int c = tid >> 4, d = tid & 15;
        float w1 = Wc[d*NH + c];
        float w2 = Wc[(NH+d)*NH + c];
        w2t[c*NH+d] = w2;
        wdt[c*NH+d] = w1 - w2;
    }
    if (tid < NH) bcs[tid] = bc[tid];
    __syncthreads();

    int i = ((blockIdx.x & 1) << 8) + tid;
    float4 hi0 = hsh[i*PITCH4+0], hi1 = hsh[i*PITCH4+1];
    float4 hi2 = hsh[i*PITCH4+2], hi3 = hsh[i*PITCH4+3];
    float sqi = sqsh[i];

    // ---- top-8 smallest d2 (unsorted set + running max) ----
    float nd[NK]; int nj[NK];
#pragma unroll
    for (int k = 0; k < NK; k++) { nd[k] = 3.4e38f; nj[k] = 0; }
    float mx = 3.4e38f; int mk = 0;

#pragma unroll 4
    for (int j = 0; j < NP; j++) {
        float4 a0 = hsh[j*PITCH4+0], a1 = hsh[j*PITCH4+1];
        float4 a2 = hsh[j*PITCH4+2], a3 = hsh[j*PITCH4+3];
        float dot = 0.f;   // same ascending chain as sq -> exact 0 self-distance
        dot=fmaf(hi0.x,a0.x,dot); dot=fmaf(hi0.y,a0.y,dot); dot=fmaf(hi0.z,a0.z,dot); dot=fmaf(hi0.w,a0.w,dot);
        dot=fmaf(hi1.x,a1.x,dot); dot=fmaf(hi1.y,a1.y,dot); dot=fmaf(hi1.z,a1.z,dot); dot=fmaf(hi1.w,a1.w,dot);
        dot=fmaf(hi2.x,a2.x,dot); dot=fmaf(hi2.y,a2.y,dot); dot=fmaf(hi2.z,a2.z,dot); dot=fmaf(hi2.w,a2.w,dot);
        dot=fmaf(hi3.x,a3.x,dot); dot=fmaf(hi3.y,a3.y,dot); dot=fmaf(hi3.z,a3.z,dot); dot=fmaf(hi3.w,a3.w,dot);
        float d2 = fmaf(-2.f, dot, sqi + sqsh[j]);
        if (d2 < mx) {
#pragma unroll
            for (int k = 0; k < NK; k++) if (k == mk) { nd[k] = d2; nj[k] = j; }
            mx = nd[0]; mk = 0;
#pragma unroll
            for (int k = 1; k < NK; k++) if (nd[k] > mx) { mx = nd[k]; mk = k; }
        }
    }

    // ---- edge MLP: m = base(i) + hj @ W2 ; max over edges, then one elu ----
    float hir[NH];
    hir[0]=hi0.x; hir[1]=hi0.y; hir[2]=hi0.z; hir[3]=hi0.w;
    hir[4]=hi1.x; hir[5]=hi1.y; hir[6]=hi1.z; hir[7]=hi1.w;
    hir[8]=hi2.x; hir[9]=hi2.y; hir[10]=hi2.z; hir[11]=hi2.w;
    hir[12]=hi3.x; hir[13]=hi3.y; hir[14]=hi3.z; hir[15]=hi3.w;

    float base[NH];
#pragma unroll
    for (int c = 0; c < NH; c++) {
        float a = bcs[c];
#pragma unroll
        for (int d = 0; d < NH; d++) a = fmaf(hir[d], wdt[c*NH+d], a);
        base[c] = a;
    }
    float acc[NH];
#pragma unroll
    for (int c = 0; c < NH; c++) acc[c] = -3.4e38f;

#pragma unroll
    for (int e = 0; e < NK; e++) {
        int j = nj[e];
        float4 b0 = hsh[j*PITCH4+0], b1 = hsh[j*PITCH4+1];
        float4 b2 = hsh[j*PITCH4+2], b3 = hsh[j*PITCH4+3];
        float hj[NH];
        hj[0]=b0.x; hj[1]=b0.y; hj[2]=b0.z; hj[3]=b0.w;
        hj[4]=b1.x; hj[5]=b1.y; hj[6]=b1.z; hj[7]=b1.w;
        hj[8]=b2.x; hj[9]=b2.y; hj[10]=b2.z; hj[11]=b2.w;
        hj[12]=b3.x; hj[13]=b3.y; hj[14]=b3.z; hj[15]=b3.w;
#pragma unroll
        for (int c = 0; c < NH; c++) {
            float a = base[c];
#pragma unroll
            for (int d = 0; d < NH; d++) a = fmaf(hj[d], w2t[c*NH+d], a);
            acc[c] = fmaxf(acc[c], a);
        }
    }

    float4 o[4];
    float* op = reinterpret_cast<float*>(o);
#pragma unroll
    for (int c = 0; c < NH; c++) op[c] = elu1(acc[c]);   // elu(max) == max(elu)
    float4* dst = reinterpret_cast<float4*>(fout + ((size_t)b*NP + i)*NH);
    dst[0]=o[0]; dst[1]=o[1]; dst[2]=o[2]; dst[3]=o[3];
}

// ----------------------------------------------------------- pool + head ----
__global__ void __launch_bounds__(256) k_pool(
    const float* __restrict__ Wo1, const float* __restrict__ bo1,
    const float* __restrict__ Wo2, const float* __restrict__ bo2,
    const float* __restrict__ Wo3, const float* __restrict__ bo3,
    float* __restrict__ out, int out_size)
{
    __shared__ float s[256];
    __shared__ float p[NH];
    int b = blockIdx.x, tid = threadIdx.x;
    int c = tid & 15, part = tid >> 4;
    const float* fg = g_f2 + (size_t)b*NP*NH;
    float acc = 0.f;
    for (int r = part; r < NP; r += 16) acc += fg[r*NH + c];
    s[tid] = acc;
    __syncthreads();
    if (tid < NH) {
        float t = 0.f;
#pragma unroll
        for (int k = 0; k < 16; k++) t += s[k*16 + tid];
        p[tid] = t * (1.0f/NP);
    }
    __syncthreads();
    if (tid == 0) {
        float t1[8];
#pragma unroll
        for (int cc = 0; cc < 8; cc++) {
            float a = bo1[cc];
#pragma unroll
            for (int d = 0; d < 16; d++) a = fmaf(p[d], Wo1[d*8+cc], a);
            t1[cc] = elu1(a);
        }
        float t2[4];
#pragma unroll
        for (int cc = 0; cc < 4; cc++) {
            float a = bo2[cc];
#pragma unroll
            for (int d = 0; d < 8; d++) a = fmaf(t1[d], Wo2[d*4+cc], a);
            t2[cc] = elu1(a);
        }
        float o = bo3[0];
#pragma unroll
        for (int d = 0; d < 4; d++) o = fmaf(t2[d], Wo3[d], o);
        out[b] = o;
        if (out_size >= 2*NB) out[NB + b] = (float)b;   // pooled_batch = arange(B)
    }
}

// --------------------------------------------------------------- launch ----
extern "C" void kernel_launch(void* const* d_in, const int* in_sizes, int n_in,
                              void* d_out, int out_size)
{
    // 12 weight/bias tensors are always the LAST 12 inputs
    // (robust to whether num_graphs survives as a tensor input).
    int wb = n_in - 12;
    const float* x   = (const float*)d_in[0];
    const float* We1 = (const float*)d_in[wb+0];
    const float* be1 = (const float*)d_in[wb+1];
    const float* We2 = (const float*)d_in[wb+2];
    const float* be2 = (const float*)d_in[wb+3];
    const float* Wc  = (const float*)d_in[wb+4];
    const float* bcp = (const float*)d_in[wb+5];
    const float* Wo1 = (const float*)d_in[wb+6];
    const float* bo1 = (const float*)d_in[wb+7];
    const float* Wo2 = (const float*)d_in[wb+8];
    const float* bo2 = (const float*)d_in[wb+9];
    const float* Wo3 = (const float*)d_in[wb+10];
    const float* bo3 = (const float*)d_in[wb+11];

    k_embed<<<NPTS/256, 256>>>(x, We1, be1, We2, be2);
    k_edgeconv<0><<<NB*2, 256>>>(Wc, bcp);
    k_edgeconv<1><<<NB*2, 256>>>(Wc, bcp);
    k_pool<<<NB, 256>>>(Wo1, bo1, Wo2, bo2, Wo3, bo3, (float*)d_out, out_size);
}

// round 2
// speedup vs baseline: 1.7697x; 1.7697x over previous
#include <cuda_runtime.h>

#define NB 256
#define NP 512
#define NH 16
#define NK 8
#define NPTS (NB*NP)
#define PITCH4 5   // float4 per point row in shared (20 floats, conflict-spread)

__device__ float g_h [NPTS*NH];
__device__ float g_f1[NPTS*NH];
__device__ float g_f2[NPTS*NH];

__device__ __forceinline__ float elu1(float x) {
    return x > 0.f ? x : (__expf(x) - 1.f);
}

// Branchless sorted insert: nd[0..7] ascending, precondition v < nd[7].
__device__ __forceinline__ void insert8(float (&nd)[NK], int (&nj)[NK], float v, int j) {
    nd[7] = v; nj[7] = j;
#pragma unroll
    for (int k = 7; k > 0; k--) {
        bool sw = nd[k] < nd[k-1];
        float td = nd[k];   int tj = nj[k];
        float ud = nd[k-1]; int uj = nj[k-1];
        nd[k]   = sw ? ud : td;  nj[k]   = sw ? uj : tj;
        nd[k-1] = sw ? td : ud;  nj[k-1] = sw ? tj : uj;
    }
}

// 4-partial dot of two 16-vectors held as float4s. MUST structurally match sq4.
__device__ __forceinline__ float dot16(const float4& x0, const float4& x1,
                                       const float4& x2, const float4& x3,
                                       const float4& y0, const float4& y1,
                                       const float4& y2, const float4& y3) {
    float p0 = fmaf(x0.x,y0.x, fmaf(x0.y,y0.y, fmaf(x0.z,y0.z, x0.w*y0.w)));
    float p1 = fmaf(x1.x,y1.x, fmaf(x1.y,y1.y, fmaf(x1.z,y1.z, x1.w*y1.w)));
    float p2 = fmaf(x2.x,y2.x, fmaf(x2.y,y2.y, fmaf(x2.z,y2.z, x2.w*y2.w)));
    float p3 = fmaf(x3.x,y3.x, fmaf(x3.y,y3.y, fmaf(x3.z,y3.z, x3.w*y3.w)));
    return (p0 + p1) + (p2 + p3);
}

// ---------------------------------------------------------------- embed ----
__global__ void __launch_bounds__(256) k_embed(
    const float* __restrict__ x,
    const float* __restrict__ We1, const float* __restrict__ be1,
    const float* __restrict__ We2, const float* __restrict__ be2)
{
    int i = blockIdx.x * 256 + threadIdx.x;
    if (i >= NPTS) return;
    float4 xv = reinterpret_cast<const float4*>(x)[i];
    float t[NH];
#pragma unroll
    for (int c = 0; c < NH; c++) {
        float a = __ldg(&be1[c]);
        a = fmaf(xv.x, __ldg(&We1[0*NH+c]), a);
        a = fmaf(xv.y, __ldg(&We1[1*NH+c]), a);
        a = fmaf(xv.z, __ldg(&We1[2*NH+c]), a);
        a = fmaf(xv.w, __ldg(&We1[3*NH+c]), a);
        t[c] = elu1(a);
    }
    float4 o[4];
    float* op = reinterpret_cast<float*>(o);
#pragma unroll
    for (int c = 0; c < NH; c++) {
        float a = __ldg(&be2[c]);
#pragma unroll
        for (int d = 0; d < NH; d++) a = fmaf(t[d], __ldg(&We2[d*NH+c]), a);
        op[c] = elu1(a);
    }
    float4* dst = reinterpret_cast<float4*>(g_h + (size_t)i*NH);
    dst[0]=o[0]; dst[1]=o[1]; dst[2]=o[2]; dst[3]=o[3];
}

// ------------------------------------------------------------- edgeconv ----
template<int PHASE>
__global__ void __launch_bounds__(256, 2) k_edgeconv(
    const float* __restrict__ Wc, const float* __restrict__ bc)
{
    __shared__ float4 hsh[NP*PITCH4];
    __shared__ float  sqsh[NP];
    __shared__ float  w2t[NH*NH];   // [c][d] = Wc[(16+d)*16+c]
    __shared__ float  wdt[NH*NH];   // [c][d] = Wc[d*16+c] - w2
    __shared__ float  bcs[NH];

    const float* hin = (PHASE == 0) ? g_h  : g_f1;
    float*       fout= (PHASE == 0) ? g_f1 : g_f2;

    int tid = threadIdx.x;
    int b   = blockIdx.x >> 1;
    const float* hg = hin + (size_t)b*NP*NH;

    for (int r = tid; r < NP; r += 256) {
        const float4* src = reinterpret_cast<const float4*>(hg + r*NH);
        float4 v0=src[0], v1=src[1], v2=src[2], v3=src[3];
        hsh[r*PITCH4+0]=v0; hsh[r*PITCH4+1]=v1;
        hsh[r*PITCH4+2]=v2; hsh[r*PITCH4+3]=v3;
        // identical structure to dot16 -> exact 0 self-distance
        sqsh[r] = dot16(v0,v1,v2,v3, v0,v1,v2,v3);
    }
    {   // W_c prep: transposed + xi/xj regroup
        int c = tid >> 4, d = tid & 15;
        float w1 = Wc[d*NH + c];
        float w2 = Wc[(NH+d)*NH + c];
        w2t[c*NH+d] = w2;
        wdt[c*NH+d] = w1 - w2;
    }
    if (tid < NH) bcs[tid] = bc[tid];
    __syncthreads();

    int i = ((blockIdx.x & 1) << 8) + tid;
    float4 hi0 = hsh[i*PITCH4+0], hi1 = hsh[i*PITCH4+1];
    float4 hi2 = hsh[i*PITCH4+2], hi3 = hsh[i*PITCH4+3];
    float sqi = sqsh[i];

    // ---- top-8 smallest d2: batch-2 j, hoisted loads, split chains ----
    float nd[NK]; int nj[NK];
#pragma unroll
    for (int k = 0; k < NK; k++) { nd[k] = 3.4e38f; nj[k] = 0; }

    for (int j = 0; j < NP; j += 2) {
        float4 a0 = hsh[j*PITCH4+0],     a1 = hsh[j*PITCH4+1];
        float4 a2 = hsh[j*PITCH4+2],     a3 = hsh[j*PITCH4+3];
        float4 c0 = hsh[(j+1)*PITCH4+0], c1 = hsh[(j+1)*PITCH4+1];
        float4 c2 = hsh[(j+1)*PITCH4+2], c3 = hsh[(j+1)*PITCH4+3];
        float sq0 = sqsh[j], sq1 = sqsh[j+1];
        float dot0 = dot16(hi0,hi1,hi2,hi3, a0,a1,a2,a3);
        float dot1 = dot16(hi0,hi1,hi2,hi3, c0,c1,c2,c3);
        float d20 = fmaf(-2.f, dot0, sqi + sq0);
        float d21 = fmaf(-2.f, dot1, sqi + sq1);
        float thr = nd[7];
        if (fminf(d20, d21) < thr) {
            if (d20 < nd[7]) insert8(nd, nj, d20, j);
            if (d21 < nd[7]) insert8(nd, nj, d21, j+1);
        }
    }

    // ---- edge MLP: m = base(i) + hj @ W2 ; max over edges, single elu ----
    float hir[NH];
    hir[0]=hi0.x; hir[1]=hi0.y; hir[2]=hi0.z; hir[3]=hi0.w;
    hir[4]=hi1.x; hir[5]=hi1.y; hir[6]=hi1.z; hir[7]=hi1.w;
    hir[8]=hi2.x; hir[9]=hi2.y; hir[10]=hi2.z; hir[11]=hi2.w;
    hir[12]=hi3.x; hir[13]=hi3.y; hir[14]=hi3.z; hir[15]=hi3.w;

    float base[NH];
#pragma unroll
    for (int c = 0; c < NH; c++) {
        float a = bcs[c];
#pragma unroll
        for (int d = 0; d < NH; d++) a = fmaf(hir[d], wdt[c*NH+d], a);
        base[c] = a;
    }
    float acc[NH];
#pragma unroll
    for (int c = 0; c < NH; c++) acc[c] = -3.4e38f;

#pragma unroll
    for (int e = 0; e < NK; e++) {
        int j = nj[e];
        float4 b0 = hsh[j*PITCH4+0], b1 = hsh[j*PITCH4+1];
        float4 b2 = hsh[j*PITCH4+2], b3 = hsh[j*PITCH4+3];
        float hj[NH];
        hj[0]=b0.x; hj[1]=b0.y; hj[2]=b0.z; hj[3]=b0.w;
        hj[4]=b1.x; hj[5]=b1.y; hj[6]=b1.z; hj[7]=b1.w;
        hj[8]=b2.x; hj[9]=b2.y; hj[10]=b2.z; hj[11]=b2.w;
        hj[12]=b3.x; hj[13]=b3.y; hj[14]=b3.z; hj[15]=b3.w;
#pragma unroll
        for (int c = 0; c < NH; c++) {
            float a = base[c];
#pragma unroll
            for (int d = 0; d < NH; d++) a = fmaf(hj[d], w2t[c*NH+d], a);
            acc[c] = fmaxf(acc[c], a);
        }
    }

    float4 o[4];
    float* op = reinterpret_cast<float*>(o);
#pragma unroll
    for (int c = 0; c < NH; c++) op[c] = elu1(acc[c]);   // elu(max) == max(elu)
    float4* dst = reinterpret_cast<float4*>(fout + ((size_t)b*NP + i)*NH);
    dst[0]=o[0]; dst[1]=o[1]; dst[2]=o[2]; dst[3]=o[3];
}

// ----------------------------------------------------------- pool + head ----
__global__ void __launch_bounds__(256) k_pool(
    const float* __restrict__ Wo1, const float* __restrict__ bo1,
    const float* __restrict__ Wo2, const float* __restrict__ bo2,
    const float* __restrict__ Wo3, const float* __restrict__ bo3,
    float* __restrict__ out, int out_size)
{
    __shared__ float s[256];
    __shared__ float p[NH];
    int b = blockIdx.x, tid = threadIdx.x;
    int c = tid & 15, part = tid >> 4;
    const float* fg = g_f2 + (size_t)b*NP*NH;
    float acc = 0.f;
    for (int r = part; r < NP; r += 16) acc += fg[r*NH + c];
    s[tid] = acc;
    __syncthreads();
    if (tid < NH) {
        float t = 0.f;
#pragma unroll
        for (int k = 0; k < 16; k++) t += s[k*16 + tid];
        p[tid] = t * (1.0f/NP);
    }
    __syncthreads();
    if (tid == 0) {
        float t1[8];
#pragma unroll
        for (int cc = 0; cc < 8; cc++) {
            float a = bo1[cc];
#pragma unroll
            for (int d = 0; d < 16; d++) a = fmaf(p[d], Wo1[d*8+cc], a);
            t1[cc] = elu1(a);
        }
        float t2[4];
#pragma unroll
        for (int cc = 0; cc < 4; cc++) {
            float a = bo2[cc];
#pragma unroll
            for (int d = 0; d < 8; d++) a = fmaf(t1[d], Wo2[d*4+cc], a);
            t2[cc] = elu1(a);
        }
        float o = bo3[0];
#pragma unroll
        for (int d = 0; d < 4; d++) o = fmaf(t2[d], Wo3[d], o);
        out[b] = o;
        if (out_size >= 2*NB) out[NB + b] = (float)b;   // pooled_batch = arange(B)
    }
}

// --------------------------------------------------------------- launch ----
extern "C" void kernel_launch(void* const* d_in, const int* in_sizes, int n_in,
                              void* d_out, int out_size)
{
    int wb = n_in - 12;
    const float* x   = (const float*)d_in[0];
    const float* We1 = (const float*)d_in[wb+0];
    const float* be1 = (const float*)d_in[wb+1];
    const float* We2 = (const float*)d_in[wb+2];
    const float* be2 = (const float*)d_in[wb+3];
    const float* Wc  = (const float*)d_in[wb+4];
    const float* bcp = (const float*)d_in[wb+5];
    const float* Wo1 = (const float*)d_in[wb+6];
    const float* bo1 = (const float*)d_in[wb+7];
    const float* Wo2 = (const float*)d_in[wb+8];
    const float* bo2 = (const float*)d_in[wb+9];
    const float* Wo3 = (const float*)d_in[wb+10];
    const float* bo3 = (const float*)d_in[wb+11];

    k_embed<<<NPTS/256, 256>>>(x, We1, be1, We2, be2);
    k_edgeconv<0><<<NB*2, 256>>>(Wc, bcp);
    k_edgeconv<1><<<NB*2, 256>>>(Wc, bcp);
    k_pool<<<NB, 256>>>(Wo1, bo1, Wo2, bo2, Wo3, bo3, (float*)d_out, out_size);
}

// round 3
// speedup vs baseline: 2.6125x; 1.4762x over previous
#include <cuda_runtime.h>

#define NB 256
#define NP 512
#define NH 16
#define NK 8
#define NPTS (NB*NP)
#define PITCH4 5   // float4 per point row in shared (20 floats, conflict-spread)

__device__ float g_h [NPTS*NH];
__device__ float g_f1[NPTS*NH];
__device__ float g_f2[NPTS*NH];

__device__ __forceinline__ float elu1(float x) {
    return x > 0.f ? x : (__expf(x) - 1.f);
}

// 4-partial dot of two 16-vectors. sq uses the same structure -> exact 0 self-distance.
__device__ __forceinline__ float dot16(const float4& x0, const float4& x1,
                                       const float4& x2, const float4& x3,
                                       const float4& y0, const float4& y1,
                                       const float4& y2, const float4& y3) {
    float p0 = fmaf(x0.x,y0.x, fmaf(x0.y,y0.y, fmaf(x0.z,y0.z, x0.w*y0.w)));
    float p1 = fmaf(x1.x,y1.x, fmaf(x1.y,y1.y, fmaf(x1.z,y1.z, x1.w*y1.w)));
    float p2 = fmaf(x2.x,y2.x, fmaf(x2.y,y2.y, fmaf(x2.z,y2.z, x2.w*y2.w)));
    float p3 = fmaf(x3.x,y3.x, fmaf(x3.y,y3.y, fmaf(x3.z,y3.z, x3.w*y3.w)));
    return (p0 + p1) + (p2 + p3);
}

// Branchless sorted-ascending insert of packed key into a[0..7] (umin/umax ladder).
__device__ __forceinline__ void ladder8(unsigned (&a)[NK], unsigned t) {
#pragma unroll
    for (int k = 0; k < NK; k++) {
        unsigned lo = umin(a[k], t);
        t = umax(a[k], t);
        a[k] = lo;
    }
}

// pack distance + index: uint order == float order for non-negative floats
__device__ __forceinline__ unsigned packkey(float d2, int j) {
    return (__float_as_uint(fmaxf(d2, 0.f)) & 0xFFFFFE00u) | (unsigned)j;
}

// ---------------------------------------------------------------- embed ----
__global__ void __launch_bounds__(256) k_embed(
    const float* __restrict__ x,
    const float* __restrict__ We1, const float* __restrict__ be1,
    const float* __restrict__ We2, const float* __restrict__ be2)
{
    int i = blockIdx.x * 256 + threadIdx.x;
    if (i >= NPTS) return;
    float4 xv = reinterpret_cast<const float4*>(x)[i];
    float t[NH];
#pragma unroll
    for (int c = 0; c < NH; c++) {
        float a = __ldg(&be1[c]);
        a = fmaf(xv.x, __ldg(&We1[0*NH+c]), a);
        a = fmaf(xv.y, __ldg(&We1[1*NH+c]), a);
        a = fmaf(xv.z, __ldg(&We1[2*NH+c]), a);
        a = fmaf(xv.w, __ldg(&We1[3*NH+c]), a);
        t[c] = elu1(a);
    }
    float4 o[4];
    float* op = reinterpret_cast<float*>(o);
#pragma unroll
    for (int c = 0; c < NH; c++) {
        float a = __ldg(&be2[c]);
#pragma unroll
        for (int d = 0; d < NH; d++) a = fmaf(t[d], __ldg(&We2[d*NH+c]), a);
        op[c] = elu1(a);
    }
    float4* dst = reinterpret_cast<float4*>(g_h + (size_t)i*NH);
    dst[0]=o[0]; dst[1]=o[1]; dst[2]=o[2]; dst[3]=o[3];
}

// ------------------------------------------------------------- edgeconv ----
template<int PHASE>
__global__ void __launch_bounds__(256, 2) k_edgeconv(
    const float* __restrict__ Wc, const float* __restrict__ bc)
{
    __shared__ float4 hsh[NP*PITCH4];   // h rows during KNN; y rows during gather
    __shared__ float  sqsh[NP];
    __shared__ float  w2t[NH*NH];   // [c][d] = Wc[(16+d)*16+c]
    __shared__ float  wdt[NH*NH];   // [c][d] = Wc[d*16+c] - w2
    __shared__ float  bcs[NH];

    const float* hin = (PHASE == 0) ? g_h  : g_f1;
    float*       fout= (PHASE == 0) ? g_f1 : g_f2;

    int tid = threadIdx.x;
    int b   = blockIdx.x >> 1;
    const float* hg = hin + (size_t)b*NP*NH;

    for (int r = tid; r < NP; r += 256) {
        const float4* src = reinterpret_cast<const float4*>(hg + r*NH);
        float4 v0=src[0], v1=src[1], v2=src[2], v3=src[3];
        hsh[r*PITCH4+0]=v0; hsh[r*PITCH4+1]=v1;
        hsh[r*PITCH4+2]=v2; hsh[r*PITCH4+3]=v3;
        sqsh[r] = dot16(v0,v1,v2,v3, v0,v1,v2,v3);
    }
    {   // W_c prep: transposed + xi/xj regroup
        int c = tid >> 4, d = tid & 15;
        float w1 = Wc[d*NH + c];
        float w2 = Wc[(NH+d)*NH + c];
        w2t[c*NH+d] = w2;
        wdt[c*NH+d] = w1 - w2;
    }
    if (tid < NH) bcs[tid] = bc[tid];
    __syncthreads();

    int i = ((blockIdx.x & 1) << 8) + tid;
    float4 hi0 = hsh[i*PITCH4+0], hi1 = hsh[i*PITCH4+1];
    float4 hi2 = hsh[i*PITCH4+2], hi3 = hsh[i*PITCH4+3];
    float sqi = sqsh[i];

    // ---- top-8 smallest d2: fully branchless packed-key ladder ----
    unsigned nd[NK];
#pragma unroll
    for (int k = 0; k < NK; k++) nd[k] = 0xFFFFFFFFu;

#pragma unroll 2
    for (int j = 0; j < NP; j += 2) {
        float4 a0 = hsh[j*PITCH4+0],     a1 = hsh[j*PITCH4+1];
        float4 a2 = hsh[j*PITCH4+2],     a3 = hsh[j*PITCH4+3];
        float4 c0 = hsh[(j+1)*PITCH4+0], c1 = hsh[(j+1)*PITCH4+1];
        float4 c2 = hsh[(j+1)*PITCH4+2], c3 = hsh[(j+1)*PITCH4+3];
        float2 sqp = *reinterpret_cast<const float2*>(&sqsh[j]);
        float dot0 = dot16(hi0,hi1,hi2,hi3, a0,a1,a2,a3);
        float dot1 = dot16(hi0,hi1,hi2,hi3, c0,c1,c2,c3);
        float d20 = fmaf(-2.f, dot0, sqi + sqp.x);
        float d21 = fmaf(-2.f, dot1, sqi + sqp.y);
        ladder8(nd, packkey(d20, j));
        ladder8(nd, packkey(d21, j+1));
    }

    // ---- base_i = bc + hi @ (W1 - W2) ----
    float hir[NH];
    hir[0]=hi0.x; hir[1]=hi0.y; hir[2]=hi0.z; hir[3]=hi0.w;
    hir[4]=hi1.x; hir[5]=hi1.y; hir[6]=hi1.z; hir[7]=hi1.w;
    hir[8]=hi2.x; hir[9]=hi2.y; hir[10]=hi2.z; hir[11]=hi2.w;
    hir[12]=hi3.x; hir[13]=hi3.y; hir[14]=hi3.z; hir[15]=hi3.w;

    float base[NH];
#pragma unroll
    for (int c = 0; c < NH; c++) {
        float a = bcs[c];
#pragma unroll
        for (int d = 0; d < NH; d++) a = fmaf(hir[d], wdt[c*NH+d], a);
        base[c] = a;
    }

    // ---- overwrite hsh with y_r = h_r @ W2 (no bias) ----
    __syncthreads();   // everyone done reading h from hsh
    float yrows[2][NH];
#pragma unroll
    for (int t2 = 0; t2 < 2; t2++) {
        int r = tid + t2*256;
        const float* hr = reinterpret_cast<const float*>(&hsh[r*PITCH4]);
        float hreg[NH];
#pragma unroll
        for (int d = 0; d < NH; d++) hreg[d] = hr[d];
#pragma unroll
        for (int c = 0; c < NH; c++) {
            float a = 0.f;
#pragma unroll
            for (int d = 0; d < NH; d++) a = fmaf(hreg[d], w2t[c*NH+d], a);
            yrows[t2][c] = a;
        }
    }
    __syncthreads();   // all reads done; now safe to overwrite
#pragma unroll
    for (int t2 = 0; t2 < 2; t2++) {
        int r = tid + t2*256;
        float* yr = reinterpret_cast<float*>(&hsh[r*PITCH4]);
#pragma unroll
        for (int c = 0; c < NH; c++) yr[c] = yrows[t2][c];
    }
    __syncthreads();

    // ---- gather: m = base_i + y_j ; max over 8 edges; single elu ----
    float acc[NH];
#pragma unroll
    for (int c = 0; c < NH; c++) acc[c] = -3.4e38f;
#pragma unroll
    for (int e = 0; e < NK; e++) {
        int j = nd[e] & 511u;
        float4 b0 = hsh[j*PITCH4+0], b1 = hsh[j*PITCH4+1];
        float4 b2 = hsh[j*PITCH4+2], b3 = hsh[j*PITCH4+3];
        const float* yj = reinterpret_cast<const float*>(&b0); // contiguous regs
        float yv[NH];
        yv[0]=b0.x; yv[1]=b0.y; yv[2]=b0.z; yv[3]=b0.w;
        yv[4]=b1.x; yv[5]=b1.y; yv[6]=b1.z; yv[7]=b1.w;
        yv[8]=b2.x; yv[9]=b2.y; yv[10]=b2.z; yv[11]=b2.w;
        yv[12]=b3.x; yv[13]=b3.y; yv[14]=b3.z; yv[15]=b3.w;
        (void)yj;
#pragma unroll
        for (int c = 0; c < NH; c++) acc[c] = fmaxf(acc[c], base[c] + yv[c]);
    }

    float4 o[4];
    float* op = reinterpret_cast<float*>(o);
#pragma unroll
    for (int c = 0; c < NH; c++) op[c] = elu1(acc[c]);   // elu(max) == max(elu)
    float4* dst = reinterpret_cast<float4*>(fout + ((size_t)b*NP + i)*NH);
    dst[0]=o[0]; dst[1]=o[1]; dst[2]=o[2]; dst[3]=o[3];
}

// ----------------------------------------------------------- pool + head ----
__global__ void __launch_bounds__(256) k_pool(
    const float* __restrict__ Wo1, const float* __restrict__ bo1,
    const float* __restrict__ Wo2, const float* __restrict__ bo2,
    const float* __restrict__ Wo3, const float* __restrict__ bo3,
    float* __restrict__ out, int out_size)
{
    __shared__ float s[256];
    __shared__ float p[NH];
    int b = blockIdx.x, tid = threadIdx.x;
    int c = tid & 15, part = tid >> 4;
    const float* fg = g_f2 + (size_t)b*NP*NH;
    float acc = 0.f;
    for (int r = part; r < NP; r += 16) acc += fg[r*NH + c];
    s[tid] = acc;
    __syncthreads();
    if (tid < NH) {
        float t = 0.f;
#pragma unroll
        for (int k = 0; k < 16; k++) t += s[k*16 + tid];
        p[tid] = t * (1.0f/NP);
    }
    __syncthreads();
    if (tid == 0) {
        float t1[8];
#pragma unroll
        for (int cc = 0; cc < 8; cc++) {
            float a = bo1[cc];
#pragma unroll
            for (int d = 0; d < 16; d++) a = fmaf(p[d], Wo1[d*8+cc], a);
            t1[cc] = elu1(a);
        }
        float t2[4];
#pragma unroll
        for (int cc = 0; cc < 4; cc++) {
            float a = bo2[cc];
#pragma unroll
            for (int d = 0; d < 8; d++) a = fmaf(t1[d], Wo2[d*4+cc], a);
            t2[cc] = elu1(a);
        }
        float o = bo3[0];
#pragma unroll
        for (int d = 0; d < 4; d++) o = fmaf(t2[d], Wo3[d], o);
        out[b] = o;
        if (out_size >= 2*NB) out[NB + b] = (float)b;   // pooled_batch = arange(B)
    }
}

// --------------------------------------------------------------- launch ----
extern "C" void kernel_launch(void* const* d_in, const int* in_sizes, int n_in,
                              void* d_out, int out_size)
{
    int wb = n_in - 12;
    const float* x   = (const float*)d_in[0];
    const float* We1 = (const float*)d_in[wb+0];
    const float* be1 = (const float*)d_in[wb+1];
    const float* We2 = (const float*)d_in[wb+2];
    const float* be2 = (const float*)d_in[wb+3];
    const float* Wc  = (const float*)d_in[wb+4];
    const float* bcp = (const float*)d_in[wb+5];
    const float* Wo1 = (const float*)d_in[wb+6];
    const float* bo1 = (const float*)d_in[wb+7];
    const float* Wo2 = (const float*)d_in[wb+8];
    const float* bo2 = (const float*)d_in[wb+9];
    const float* Wo3 = (const float*)d_in[wb+10];
    const float* bo3 = (const float*)d_in[wb+11];

    k_embed<<<NPTS/256, 256>>>(x, We1, be1, We2, be2);
    k_edgeconv<0><<<NB*2, 256>>>(Wc, bcp);
    k_edgeconv<1><<<NB*2, 256>>>(Wc, bcp);
    k_pool<<<NB, 256>>>(Wo1, bo1, Wo2, bo2, Wo3, bo3, (float*)d_out, out_size);
}

// round 4
// speedup vs baseline: 2.9285x; 1.1210x over previous
#include <cuda_runtime.h>

#define NB 256
#define NP 512
#define NH 16
#define NK 8
#define NPTS (NB*NP)
#define HTP 520           // transposed pitch (floats); 2080B rows, 16B-aligned
#define YP  20            // y-row pitch (floats), bank-spread for gather

typedef unsigned long long ull;

__device__ float g_h [NPTS*NH];
__device__ float g_f1[NPTS*NH];
__device__ float g_f2[NPTS*NH];

__device__ __forceinline__ float elu1(float x) {
    return x > 0.f ? x : (__expf(x) - 1.f);
}

// ---- f32x2 packed helpers ----
__device__ __forceinline__ ull fma2(ull a, ull b, ull c) {
    ull d; asm("fma.rn.f32x2 %0, %1, %2, %3;" : "=l"(d) : "l"(a), "l"(b), "l"(c)); return d;
}
__device__ __forceinline__ ull add2(ull a, ull b) {
    ull d; asm("add.rn.f32x2 %0, %1, %2;" : "=l"(d) : "l"(a), "l"(b)); return d;
}
__device__ __forceinline__ ull pack2(float lo, float hi) {
    ull d; asm("mov.b64 %0, {%1, %2};" : "=l"(d) : "f"(lo), "f"(hi)); return d;
}
__device__ __forceinline__ float2 unpack2(ull v) {
    float lo, hi; asm("mov.b64 {%0, %1}, %2;" : "=f"(lo), "=f"(hi) : "l"(v));
    return make_float2(lo, hi);
}

// Branchless sorted-ascending insert (umin/umax ladder).
__device__ __forceinline__ void ladder8(unsigned (&a)[NK], unsigned t) {
#pragma unroll
    for (int k = 0; k < NK; k++) {
        unsigned lo = umin(a[k], t);
        t = umax(a[k], t);
        a[k] = lo;
    }
}
// pack distance + index: uint order == float order for non-negative floats
__device__ __forceinline__ unsigned packkey(float d2, int j) {
    return (__float_as_uint(fmaxf(d2, 0.f)) & 0xFFFFFE00u) | (unsigned)j;
}

// ---------------------------------------------------------------- embed ----
__global__ void __launch_bounds__(256) k_embed(
    const float* __restrict__ x,
    const float* __restrict__ We1, const float* __restrict__ be1,
    const float* __restrict__ We2, const float* __restrict__ be2)
{
    int i = blockIdx.x * 256 + threadIdx.x;
    if (i >= NPTS) return;
    float4 xv = reinterpret_cast<const float4*>(x)[i];
    float t[NH];
#pragma unroll
    for (int c = 0; c < NH; c++) {
        float a = __ldg(&be1[c]);
        a = fmaf(xv.x, __ldg(&We1[0*NH+c]), a);
        a = fmaf(xv.y, __ldg(&We1[1*NH+c]), a);
        a = fmaf(xv.z, __ldg(&We1[2*NH+c]), a);
        a = fmaf(xv.w, __ldg(&We1[3*NH+c]), a);
        t[c] = elu1(a);
    }
    float4 o[4];
    float* op = reinterpret_cast<float*>(o);
#pragma unroll
    for (int c = 0; c < NH; c++) {
        float a = __ldg(&be2[c]);
#pragma unroll
        for (int d = 0; d < NH; d++) a = fmaf(t[d], __ldg(&We2[d*NH+c]), a);
        op[c] = elu1(a);
    }
    float4* dst = reinterpret_cast<float4*>(g_h + (size_t)i*NH);
    dst[0]=o[0]; dst[1]=o[1]; dst[2]=o[2]; dst[3]=o[3];
}

// ------------------------------------------------------------- edgeconv ----
template<int PHASE>
__global__ void __launch_bounds__(256, 2) k_edgeconv(
    const float* __restrict__ Wc, const float* __restrict__ bc)
{
    // region: hT[16][HTP] (transposed h) during KNN; y[512][YP] during gather
    __shared__ __align__(16) float region[NP*YP];      // 40KB  (>= 16*HTP)
    __shared__ __align__(16) float sqsh[NP];
    __shared__ float w2t[NH*NH];   // [c][d] = Wc[(16+d)*16+c]
    __shared__ float wdt[NH*NH];   // [c][d] = Wc[d*16+c] - w2
    __shared__ float bcs[NH];

    const float* hin = (PHASE == 0) ? g_h  : g_f1;
    float*       fout= (PHASE == 0) ? g_f1 : g_f2;

    int tid = threadIdx.x;
    int b   = blockIdx.x >> 1;
    const float* hg = hin + (size_t)b*NP*NH;

    // load + transpose + sq (split chains d0-7 / d8-15 to match packed dot)
    for (int r = tid; r < NP; r += 256) {
        const float4* src = reinterpret_cast<const float4*>(hg + r*NH);
        float4 v0=src[0], v1=src[1], v2=src[2], v3=src[3];
        float f[NH];
        f[0]=v0.x; f[1]=v0.y; f[2]=v0.z; f[3]=v0.w;
        f[4]=v1.x; f[5]=v1.y; f[6]=v1.z; f[7]=v1.w;
        f[8]=v2.x; f[9]=v2.y; f[10]=v2.z; f[11]=v2.w;
        f[12]=v3.x; f[13]=v3.y; f[14]=v3.z; f[15]=v3.w;
#pragma unroll
        for (int d = 0; d < NH; d++) region[d*HTP + r] = f[d];
        float sA = 0.f, sB = 0.f;
#pragma unroll
        for (int d = 0; d < 8; d++)  sA = fmaf(f[d], f[d], sA);
#pragma unroll
        for (int d = 8; d < 16; d++) sB = fmaf(f[d], f[d], sB);
        sqsh[r] = sA + sB;
    }
    {   // W_c prep: transposed + xi/xj regroup
        int c = tid >> 4, d = tid & 15;
        float w1 = Wc[d*NH + c];
        float w2 = Wc[(NH+d)*NH + c];
        w2t[c*NH+d] = w2;
        wdt[c*NH+d] = w1 - w2;
    }
    if (tid < NH) bcs[tid] = bc[tid];
    __syncthreads();

    int i = ((blockIdx.x & 1) << 8) + tid;
    float hir[NH];
#pragma unroll
    for (int d = 0; d < NH; d++) hir[d] = region[d*HTP + i];
    float sqi = sqsh[i];
    ull hi2[NH];
#pragma unroll
    for (int d = 0; d < NH; d++) hi2[d] = pack2(hir[d], hir[d]);
    ull sqi2 = pack2(sqi, sqi);
    ull neg2 = pack2(-2.f, -2.f);

    // base_i = bc + hi @ (W1 - W2)
    float base[NH];
#pragma unroll
    for (int c = 0; c < NH; c++) {
        float a = bcs[c];
#pragma unroll
        for (int d = 0; d < NH; d++) a = fmaf(hir[d], wdt[c*NH+d], a);
        base[c] = a;
    }

    // ---- top-8 smallest d2: packed f32x2 dots + branchless key ladder ----
    unsigned nd[NK];
#pragma unroll
    for (int k = 0; k < NK; k++) nd[k] = 0xFFFFFFFFu;

#pragma unroll 1
    for (int j = 0; j < NP; j += 4) {
        ull accA01 = 0ull, accB01 = 0ull, accA23 = 0ull, accB23 = 0ull;
#pragma unroll
        for (int d = 0; d < 8; d++) {
            ulonglong2 v = *reinterpret_cast<const ulonglong2*>(&region[d*HTP + j]);
            accA01 = fma2(hi2[d], v.x, accA01);
            accA23 = fma2(hi2[d], v.y, accA23);
        }
#pragma unroll
        for (int d = 8; d < 16; d++) {
            ulonglong2 v = *reinterpret_cast<const ulonglong2*>(&region[d*HTP + j]);
            accB01 = fma2(hi2[d], v.x, accB01);
            accB23 = fma2(hi2[d], v.y, accB23);
        }
        ull dot01 = add2(accA01, accB01);
        ull dot23 = add2(accA23, accB23);
        ulonglong2 sv = *reinterpret_cast<const ulonglong2*>(&sqsh[j]);
        ull d201 = fma2(neg2, dot01, add2(sqi2, sv.x));
        ull d223 = fma2(neg2, dot23, add2(sqi2, sv.y));
        float2 p01 = unpack2(d201);
        float2 p23 = unpack2(d223);
        ladder8(nd, packkey(p01.x, j));
        ladder8(nd, packkey(p01.y, j+1));
        ladder8(nd, packkey(p23.x, j+2));
        ladder8(nd, packkey(p23.y, j+3));
    }

    // ---- y_r = h_r @ W2 into registers, then overwrite region (pitch YP) ----
    float yrows[2][NH];
#pragma unroll
    for (int t2 = 0; t2 < 2; t2++) {
        int r = tid + t2*256;
        float f[NH];
#pragma unroll
        for (int d = 0; d < NH; d++) f[d] = region[d*HTP + r];
#pragma unroll
        for (int c = 0; c < NH; c++) {
            float a = 0.f;
#pragma unroll
            for (int d = 0; d < NH; d++) a = fmaf(f[d], w2t[c*NH+d], a);
            yrows[t2][c] = a;
        }
    }
    __syncthreads();   // all hT reads complete
#pragma unroll
    for (int t2 = 0; t2 < 2; t2++) {
        int r = tid + t2*256;
#pragma unroll
        for (int c = 0; c < NH; c++) region[r*YP + c] = yrows[t2][c];
    }
    __syncthreads();

    // ---- gather: m = base_i + y_j ; max over 8 edges; single elu ----
    float acc[NH];
#pragma unroll
    for (int c = 0; c < NH; c++) acc[c] = -3.4e38f;
#pragma unroll
    for (int e = 0; e < NK; e++) {
        int j = nd[e] & 511u;
        const float4* yp = reinterpret_cast<const float4*>(&region[j*YP]);
        float4 b0 = yp[0], b1 = yp[1], b2 = yp[2], b3 = yp[3];
        float yv[NH];
        yv[0]=b0.x; yv[1]=b0.y; yv[2]=b0.z; yv[3]=b0.w;
        yv[4]=b1.x; yv[5]=b1.y; yv[6]=b1.z; yv[7]=b1.w;
        yv[8]=b2.x; yv[9]=b2.y; yv[10]=b2.z; yv[11]=b2.w;
        yv[12]=b3.x; yv[13]=b3.y; yv[14]=b3.z; yv[15]=b3.w;
#pragma unroll
        for (int c = 0; c < NH; c++) acc[c] = fmaxf(acc[c], base[c] + yv[c]);
    }

    float4 o[4];
    float* op = reinterpret_cast<float*>(o);
#pragma unroll
    for (int c = 0; c < NH; c++) op[c] = elu1(acc[c]);   // elu(max) == max(elu)
    float4* dst = reinterpret_cast<float4*>(fout + ((size_t)b*NP + i)*NH);
    dst[0]=o[0]; dst[1]=o[1]; dst[2]=o[2]; dst[3]=o[3];
}

// ----------------------------------------------------------- pool + head ----
__global__ void __launch_bounds__(256) k_pool(
    const float* __restrict__ Wo1, const float* __restrict__ bo1,
    const float* __restrict__ Wo2, const float* __restrict__ bo2,
    const float* __restrict__ Wo3, const float* __restrict__ bo3,
    float* __restrict__ out, int out_size)
{
    __shared__ float s[256];
    __shared__ float p[NH];
    int b = blockIdx.x, tid = threadIdx.x;
    int c = tid & 15, part = tid >> 4;
    const float* fg = g_f2 + (size_t)b*NP*NH;
    float acc = 0.f;
    for (int r = part; r < NP; r += 16) acc += fg[r*NH + c];
    s[tid] = acc;
    __syncthreads();
    if (tid < NH) {
        float t = 0.f;
#pragma unroll
        for (int k = 0; k < 16; k++) t += s[k*16 + tid];
        p[tid] = t * (1.0f/NP);
    }
    __syncthreads();
    if (tid == 0) {
        float t1[8];
#pragma unroll
        for (int cc = 0; cc < 8; cc++) {
            float a = bo1[cc];
#pragma unroll
            for (int d = 0; d < 16; d++) a = fmaf(p[d], Wo1[d*8+cc], a);
            t1[cc] = elu1(a);
        }
        float t2[4];
#pragma unroll
        for (int cc = 0; cc < 4; cc++) {
            float a = bo2[cc];
#pragma unroll
            for (int d = 0; d < 8; d++) a = fmaf(t1[d], Wo2[d*4+cc], a);
            t2[cc] = elu1(a);
        }
        float o = bo3[0];
#pragma unroll
        for (int d = 0; d < 4; d++) o = fmaf(t2[d], Wo3[d], o);
        out[b] = o;
        if (out_size >= 2*NB) out[NB + b] = (float)b;   // pooled_batch = arange(B)
    }
}

// --------------------------------------------------------------- launch ----
extern "C" void kernel_launch(void* const* d_in, const int* in_sizes, int n_in,
                              void* d_out, int out_size)
{
    int wb = n_in - 12;
    const float* x   = (const float*)d_in[0];
    const float* We1 = (const float*)d_in[wb+0];
    const float* be1 = (const float*)d_in[wb+1];
    const float* We2 = (const float*)d_in[wb+2];
    const float* be2 = (const float*)d_in[wb+3];
    const float* Wc  = (const float*)d_in[wb+4];
    const float* bcp = (const float*)d_in[wb+5];
    const float* Wo1 = (const float*)d_in[wb+6];
    const float* bo1 = (const float*)d_in[wb+7];
    const float* Wo2 = (const float*)d_in[wb+8];
    const float* bo2 = (const float*)d_in[wb+9];
    const float* Wo3 = (const float*)d_in[wb+10];
    const float* bo3 = (const float*)d_in[wb+11];

    k_embed<<<NPTS/256, 256>>>(x, We1, be1, We2, be2);
    k_edgeconv<0><<<NB*2, 256>>>(Wc, bcp);
    k_edgeconv<1><<<NB*2, 256>>>(Wc, bcp);
    k_pool<<<NB, 256>>>(Wo1, bo1, Wo2, bo2, Wo3, bo3, (float*)d_out, out_size);
}

// round 5
// speedup vs baseline: 3.4960x; 1.1938x over previous
#include <cuda_runtime.h>

#define NB 256
#define NP 512
#define NH 16
#define NK 8
#define NPTS (NB*NP)
#define HTP 520           // transposed pitch (floats); 2080B rows, 16B-aligned
#define YP  20            // y-row pitch (floats), bank-spread for gather

typedef unsigned long long ull;

__device__ float g_h [NPTS*NH];
__device__ float g_f1[NPTS*NH];
__device__ float g_f2[NPTS*NH];

__device__ __forceinline__ float elu1(float x) {
    return x > 0.f ? x : (__expf(x) - 1.f);
}

// ---- f32x2 packed helpers ----
__device__ __forceinline__ ull fma2(ull a, ull b, ull c) {
    ull d; asm("fma.rn.f32x2 %0, %1, %2, %3;" : "=l"(d) : "l"(a), "l"(b), "l"(c)); return d;
}
__device__ __forceinline__ ull add2(ull a, ull b) {
    ull d; asm("add.rn.f32x2 %0, %1, %2;" : "=l"(d) : "l"(a), "l"(b)); return d;
}
__device__ __forceinline__ ull pack2(float lo, float hi) {
    ull d; asm("mov.b64 %0, {%1, %2};" : "=l"(d) : "f"(lo), "f"(hi)); return d;
}
__device__ __forceinline__ float2 unpack2(ull v) {
    float lo, hi; asm("mov.b64 {%0, %1}, %2;" : "=f"(lo), "=f"(hi) : "l"(v));
    return make_float2(lo, hi);
}

// pack distance + index: uint order == float order for non-negative floats
__device__ __forceinline__ unsigned packkey(float d2, int j) {
    return (__float_as_uint(fmaxf(d2, 0.f)) & 0xFFFFFE00u) | (unsigned)j;
}

#define CE(x, y) { unsigned _lo = umin(x, y); y = umax(x, y); x = _lo; }

// Optimal 19-CE sorting network for 8 keys (ascending).
__device__ __forceinline__ void sort8(unsigned (&k)[8]) {
    CE(k[0],k[1]); CE(k[2],k[3]); CE(k[4],k[5]); CE(k[6],k[7]);
    CE(k[0],k[2]); CE(k[1],k[3]); CE(k[4],k[6]); CE(k[5],k[7]);
    CE(k[1],k[2]); CE(k[5],k[6]); CE(k[0],k[4]); CE(k[3],k[7]);
    CE(k[1],k[5]); CE(k[2],k[6]);
    CE(k[1],k[4]); CE(k[3],k[6]);
    CE(k[2],k[4]); CE(k[3],k[5]);
    CE(k[3],k[4]);
}

// nd (asc) <- 8 smallest of nd ∪ k (k asc).  min-pair + bitonic clean-up.
__device__ __forceinline__ void mergeTop8(unsigned (&nd)[NK], const unsigned (&k)[8]) {
    unsigned L[8];
#pragma unroll
    for (int i = 0; i < 8; i++) L[i] = umin(nd[i], k[7-i]);   // bitonic, = 8 smallest
    CE(L[0],L[4]); CE(L[1],L[5]); CE(L[2],L[6]); CE(L[3],L[7]);
    CE(L[0],L[2]); CE(L[1],L[3]); CE(L[4],L[6]); CE(L[5],L[7]);
    CE(L[0],L[1]); CE(L[2],L[3]); CE(L[4],L[5]); CE(L[6],L[7]);
#pragma unroll
    for (int i = 0; i < 8; i++) nd[i] = L[i];
}

// ---------------------------------------------------------------- embed ----
__global__ void __launch_bounds__(256) k_embed(
    const float* __restrict__ x,
    const float* __restrict__ We1, const float* __restrict__ be1,
    const float* __restrict__ We2, const float* __restrict__ be2)
{
    int i = blockIdx.x * 256 + threadIdx.x;
    if (i >= NPTS) return;
    float4 xv = reinterpret_cast<const float4*>(x)[i];
    float t[NH];
#pragma unroll
    for (int c = 0; c < NH; c++) {
        float a = __ldg(&be1[c]);
        a = fmaf(xv.x, __ldg(&We1[0*NH+c]), a);
        a = fmaf(xv.y, __ldg(&We1[1*NH+c]), a);
        a = fmaf(xv.z, __ldg(&We1[2*NH+c]), a);
        a = fmaf(xv.w, __ldg(&We1[3*NH+c]), a);
        t[c] = elu1(a);
    }
    float4 o[4];
    float* op = reinterpret_cast<float*>(o);
#pragma unroll
    for (int c = 0; c < NH; c++) {
        float a = __ldg(&be2[c]);
#pragma unroll
        for (int d = 0; d < NH; d++) a = fmaf(t[d], __ldg(&We2[d*NH+c]), a);
        op[c] = elu1(a);
    }
    float4* dst = reinterpret_cast<float4*>(g_h + (size_t)i*NH);
    dst[0]=o[0]; dst[1]=o[1]; dst[2]=o[2]; dst[3]=o[3];
}

// ------------------------------------------------------------- edgeconv ----
template<int PHASE>
__global__ void __launch_bounds__(256, 2) k_edgeconv(
    const float* __restrict__ Wc, const float* __restrict__ bc)
{
    // region: hT[16][HTP] (transposed h) during KNN; y[512][YP] during gather
    __shared__ __align__(16) float region[NP*YP];      // 40KB  (>= 16*HTP)
    __shared__ __align__(16) float sqsh[NP];
    __shared__ float w2t[NH*NH];   // [c][d] = Wc[(16+d)*16+c]
    __shared__ float wdt[NH*NH];   // [c][d] = Wc[d*16+c] - w2
    __shared__ float bcs[NH];

    const float* hin = (PHASE == 0) ? g_h  : g_f1;
    float*       fout= (PHASE == 0) ? g_f1 : g_f2;

    int tid = threadIdx.x;
    int b   = blockIdx.x >> 1;
    const float* hg = hin + (size_t)b*NP*NH;

    // load + transpose + sq (split chains d0-7 / d8-15 to match packed dot)
    for (int r = tid; r < NP; r += 256) {
        const float4* src = reinterpret_cast<const float4*>(hg + r*NH);
        float4 v0=src[0], v1=src[1], v2=src[2], v3=src[3];
        float f[NH];
        f[0]=v0.x; f[1]=v0.y; f[2]=v0.z; f[3]=v0.w;
        f[4]=v1.x; f[5]=v1.y; f[6]=v1.z; f[7]=v1.w;
        f[8]=v2.x; f[9]=v2.y; f[10]=v2.z; f[11]=v2.w;
        f[12]=v3.x; f[13]=v3.y; f[14]=v3.z; f[15]=v3.w;
#pragma unroll
        for (int d = 0; d < NH; d++) region[d*HTP + r] = f[d];
        float sA = 0.f, sB = 0.f;
#pragma unroll
        for (int d = 0; d < 8; d++)  sA = fmaf(f[d], f[d], sA);
#pragma unroll
        for (int d = 8; d < 16; d++) sB = fmaf(f[d], f[d], sB);
        sqsh[r] = sA + sB;
    }
    {   // W_c prep: transposed + xi/xj regroup
        int c = tid >> 4, d = tid & 15;
        float w1 = Wc[d*NH + c];
        float w2 = Wc[(NH+d)*NH + c];
        w2t[c*NH+d] = w2;
        wdt[c*NH+d] = w1 - w2;
    }
    if (tid < NH) bcs[tid] = bc[tid];
    __syncthreads();

    int i = ((blockIdx.x & 1) << 8) + tid;
    float hir[NH];
#pragma unroll
    for (int d = 0; d < NH; d++) hir[d] = region[d*HTP + i];
    float sqi = sqsh[i];
    ull hi2[NH];
#pragma unroll
    for (int d = 0; d < NH; d++) hi2[d] = pack2(hir[d], hir[d]);
    ull sqi2 = pack2(sqi, sqi);
    ull neg2 = pack2(-2.f, -2.f);

    // ---- top-8 smallest d2: f32x2 dots + batched sort-merge selection ----
    unsigned nd[NK];
#pragma unroll
    for (int k = 0; k < NK; k++) nd[k] = 0xFFFFFFFFu;

#pragma unroll 1
    for (int j = 0; j < NP; j += 8) {
        ull accA[4], accB[4];
#pragma unroll
        for (int p = 0; p < 4; p++) { accA[p] = 0ull; accB[p] = 0ull; }
#pragma unroll
        for (int d = 0; d < 8; d++) {
            ulonglong2 v01 = *reinterpret_cast<const ulonglong2*>(&region[d*HTP + j]);
            ulonglong2 v23 = *reinterpret_cast<const ulonglong2*>(&region[d*HTP + j + 4]);
            accA[0] = fma2(hi2[d], v01.x, accA[0]);
            accA[1] = fma2(hi2[d], v01.y, accA[1]);
            accA[2] = fma2(hi2[d], v23.x, accA[2]);
            accA[3] = fma2(hi2[d], v23.y, accA[3]);
        }
#pragma unroll
        for (int d = 8; d < 16; d++) {
            ulonglong2 v01 = *reinterpret_cast<const ulonglong2*>(&region[d*HTP + j]);
            ulonglong2 v23 = *reinterpret_cast<const ulonglong2*>(&region[d*HTP + j + 4]);
            accB[0] = fma2(hi2[d], v01.x, accB[0]);
            accB[1] = fma2(hi2[d], v01.y, accB[1]);
            accB[2] = fma2(hi2[d], v23.x, accB[2]);
            accB[3] = fma2(hi2[d], v23.y, accB[3]);
        }
        ulonglong2 s01 = *reinterpret_cast<const ulonglong2*>(&sqsh[j]);
        ulonglong2 s23 = *reinterpret_cast<const ulonglong2*>(&sqsh[j + 4]);
        ull sq4[4]; sq4[0]=s01.x; sq4[1]=s01.y; sq4[2]=s23.x; sq4[3]=s23.y;
        unsigned kk[8];
#pragma unroll
        for (int p = 0; p < 4; p++) {
            ull dot = add2(accA[p], accB[p]);
            ull d2  = fma2(neg2, dot, add2(sqi2, sq4[p]));
            float2 pr = unpack2(d2);
            kk[2*p+0] = packkey(pr.x, j + 2*p);
            kk[2*p+1] = packkey(pr.y, j + 2*p + 1);
        }
        sort8(kk);
        mergeTop8(nd, kk);
    }

    // base_i = bc + hi @ (W1 - W2)
    float base[NH];
#pragma unroll
    for (int c = 0; c < NH; c++) {
        float a = bcs[c];
#pragma unroll
        for (int d = 0; d < NH; d++) a = fmaf(hir[d], wdt[c*NH+d], a);
        base[c] = a;
    }

    // ---- y_r = h_r @ W2 into registers, then overwrite region (pitch YP) ----
    float yrows[2][NH];
#pragma unroll
    for (int t2 = 0; t2 < 2; t2++) {
        int r = tid + t2*256;
        float f[NH];
#pragma unroll
        for (int d = 0; d < NH; d++) f[d] = region[d*HTP + r];
#pragma unroll
        for (int c = 0; c < NH; c++) {
            float a = 0.f;
#pragma unroll
            for (int d = 0; d < NH; d++) a = fmaf(f[d], w2t[c*NH+d], a);
            yrows[t2][c] = a;
        }
    }
    __syncthreads();   // all hT reads complete
#pragma unroll
    for (int t2 = 0; t2 < 2; t2++) {
        int r = tid + t2*256;
#pragma unroll
        for (int c = 0; c < NH; c++) region[r*YP + c] = yrows[t2][c];
    }
    __syncthreads();

    // ---- gather: m = base_i + y_j ; max over 8 edges; single elu ----
    float acc[NH];
#pragma unroll
    for (int c = 0; c < NH; c++) acc[c] = -3.4e38f;
#pragma unroll
    for (int e = 0; e < NK; e++) {
        int j = nd[e] & 511u;
        const float4* yp = reinterpret_cast<const float4*>(&region[j*YP]);
        float4 b0 = yp[0], b1 = yp[1], b2 = yp[2], b3 = yp[3];
        float yv[NH];
        yv[0]=b0.x; yv[1]=b0.y; yv[2]=b0.z; yv[3]=b0.w;
        yv[4]=b1.x; yv[5]=b1.y; yv[6]=b1.z; yv[7]=b1.w;
        yv[8]=b2.x; yv[9]=b2.y; yv[10]=b2.z; yv[11]=b2.w;
        yv[12]=b3.x; yv[13]=b3.y; yv[14]=b3.z; yv[15]=b3.w;
#pragma unroll
        for (int c = 0; c < NH; c++) acc[c] = fmaxf(acc[c], base[c] + yv[c]);
    }

    float4 o[4];
    float* op = reinterpret_cast<float*>(o);
#pragma unroll
    for (int c = 0; c < NH; c++) op[c] = elu1(acc[c]);   // elu(max) == max(elu)
    float4* dst = reinterpret_cast<float4*>(fout + ((size_t)b*NP + i)*NH);
    dst[0]=o[0]; dst[1]=o[1]; dst[2]=o[2]; dst[3]=o[3];
}

// ----------------------------------------------------------- pool + head ----
__global__ void __launch_bounds__(256) k_pool(
    const float* __restrict__ Wo1, const float* __restrict__ bo1,
    const float* __restrict__ Wo2, const float* __restrict__ bo2,
    const float* __restrict__ Wo3, const float* __restrict__ bo3,
    float* __restrict__ out, int out_size)
{
    __shared__ float s[256];
    __shared__ float p[NH];
    int b = blockIdx.x, tid = threadIdx.x;
    int c = tid & 15, part = tid >> 4;
    const float* fg = g_f2 + (size_t)b*NP*NH;
    float acc = 0.f;
    for (int r = part; r < NP; r += 16) acc += fg[r*NH + c];
    s[tid] = acc;
    __syncthreads();
    if (tid < NH) {
        float t = 0.f;
#pragma unroll
        for (int k = 0; k < 16; k++) t += s[k*16 + tid];
        p[tid] = t * (1.0f/NP);
    }
    __syncthreads();
    if (tid == 0) {
        float t1[8];
#pragma unroll
        for (int cc = 0; cc < 8; cc++) {
            float a = bo1[cc];
#pragma unroll
            for (int d = 0; d < 16; d++) a = fmaf(p[d], Wo1[d*8+cc], a);
            t1[cc] = elu1(a);
        }
        float t2[4];
#pragma unroll
        for (int cc = 0; cc < 4; cc++) {
            float a = bo2[cc];
#pragma unroll
            for (int d = 0; d < 8; d++) a = fmaf(t1[d], Wo2[d*4+cc], a);
            t2[cc] = elu1(a);
        }
        float o = bo3[0];
#pragma unroll
        for (int d = 0; d < 4; d++) o = fmaf(t2[d], Wo3[d], o);
        out[b] = o;
        if (out_size >= 2*NB) out[NB + b] = (float)b;   // pooled_batch = arange(B)
    }
}

// --------------------------------------------------------------- launch ----
extern "C" void kernel_launch(void* const* d_in, const int* in_sizes, int n_in,
                              void* d_out, int out_size)
{
    int wb = n_in - 12;
    const float* x   = (const float*)d_in[0];
    const float* We1 = (const float*)d_in[wb+0];
    const float* be1 = (const float*)d_in[wb+1];
    const float* We2 = (const float*)d_in[wb+2];
    const float* be2 = (const float*)d_in[wb+3];
    const float* Wc  = (const float*)d_in[wb+4];
    const float* bcp = (const float*)d_in[wb+5];
    const float* Wo1 = (const float*)d_in[wb+6];
    const float* bo1 = (const float*)d_in[wb+7];
    const float* Wo2 = (const float*)d_in[wb+8];
    const float* bo2 = (const float*)d_in[wb+9];
    const float* Wo3 = (const float*)d_in[wb+10];
    const float* bo3 = (const float*)d_in[wb+11];

    k_embed<<<NPTS/256, 256>>>(x, We1, be1, We2, be2);
    k_edgeconv<0><<<NB*2, 256>>>(Wc, bcp);
    k_edgeconv<1><<<NB*2, 256>>>(Wc, bcp);
    k_pool<<<NB, 256>>>(Wo1, bo1, Wo2, bo2, Wo3, bo3, (float*)d_out, out_size);
}

// round 6
// speedup vs baseline: 3.5304x; 1.0099x over previous
#include <cuda_runtime.h>

#define NB 256
#define NP 512
#define NH 16
#define NK 8
#define NPTS (NB*NP)
#define HTP 520           // transposed pitch (floats); 2080B rows, 16B-aligned
#define YP  20            // y-row pitch (floats), bank-spread for gather
#define RP  17            // pool-reduce row pitch

typedef unsigned long long ull;

__device__ float g_f1  [NPTS*NH];
__device__ float g_pool[2*NB*NH];   // per half-graph channel sums

__device__ __forceinline__ float elu1(float x) {
    return x > 0.f ? x : (__expf(x) - 1.f);
}

// ---- f32x2 packed helpers ----
__device__ __forceinline__ ull fma2(ull a, ull b, ull c) {
    ull d; asm("fma.rn.f32x2 %0, %1, %2, %3;" : "=l"(d) : "l"(a), "l"(b), "l"(c)); return d;
}
__device__ __forceinline__ ull add2(ull a, ull b) {
    ull d; asm("add.rn.f32x2 %0, %1, %2;" : "=l"(d) : "l"(a), "l"(b)); return d;
}
__device__ __forceinline__ ull pack2(float lo, float hi) {
    ull d; asm("mov.b64 %0, {%1, %2};" : "=l"(d) : "f"(lo), "f"(hi)); return d;
}
__device__ __forceinline__ float2 unpack2(ull v) {
    float lo, hi; asm("mov.b64 {%0, %1}, %2;" : "=f"(lo), "=f"(hi) : "l"(v));
    return make_float2(lo, hi);
}

// key = bits(d2 + 1.0) with low 9 bits replaced by j.
// d2+1 >= ~1.0 (positive, normal) so uint order == float order; no clamp needed.
__device__ __forceinline__ unsigned packkey(float d2p1, int j) {
    return (__float_as_uint(d2p1) & 0xFFFFFE00u) | (unsigned)j;
}

#define CE(x, y) { unsigned _lo = umin(x, y); y = umax(x, y); x = _lo; }

// Optimal 19-CE sorting network for 8 keys (ascending).
__device__ __forceinline__ void sort8(unsigned (&k)[8]) {
    CE(k[0],k[1]); CE(k[2],k[3]); CE(k[4],k[5]); CE(k[6],k[7]);
    CE(k[0],k[2]); CE(k[1],k[3]); CE(k[4],k[6]); CE(k[5],k[7]);
    CE(k[1],k[2]); CE(k[5],k[6]); CE(k[0],k[4]); CE(k[3],k[7]);
    CE(k[1],k[5]); CE(k[2],k[6]);
    CE(k[1],k[4]); CE(k[3],k[6]);
    CE(k[2],k[4]); CE(k[3],k[5]);
    CE(k[3],k[4]);
}

// nd (asc) <- 8 smallest of nd ∪ k (k asc).  min-pair + bitonic clean-up.
__device__ __forceinline__ void mergeTop8(unsigned (&nd)[NK], const unsigned (&k)[8]) {
    unsigned L[8];
#pragma unroll
    for (int i = 0; i < 8; i++) L[i] = umin(nd[i], k[7-i]);
    CE(L[0],L[4]); CE(L[1],L[5]); CE(L[2],L[6]); CE(L[3],L[7]);
    CE(L[0],L[2]); CE(L[1],L[3]); CE(L[4],L[6]); CE(L[5],L[7]);
    CE(L[0],L[1]); CE(L[2],L[3]); CE(L[4],L[5]); CE(L[6],L[7]);
#pragma unroll
    for (int i = 0; i < 8; i++) nd[i] = L[i];
}

// ------------------------------------------------------------- edgeconv ----
// PHASE 0: embed(x) -> conv -> g_f1      (embed fused in prologue)
// PHASE 1: g_f1 -> conv -> g_pool sums   (pool fused in epilogue)
template<int PHASE>
__global__ void __launch_bounds__(256, 2) k_edgeconv(
    const float* __restrict__ x,
    const float* __restrict__ We1, const float* __restrict__ be1,
    const float* __restrict__ We2, const float* __restrict__ be2,
    const float* __restrict__ Wc,  const float* __restrict__ bc)
{
    __shared__ __align__(16) float region[NP*YP];    // hT -> y -> pool scratch
    __shared__ __align__(16) float sqsh[NP];
    __shared__ float w2t[NH*NH];   // [c][d] = Wc[(16+d)*16+c]
    __shared__ float wdt[NH*NH];   // [c][d] = Wc[d*16+c] - w2
    __shared__ float bcs[NH];

    int tid = threadIdx.x;
    int b   = blockIdx.x >> 1;

    // ---- prologue: produce h rows (transposed) + squared norms ----
    for (int r = tid; r < NP; r += 256) {
        float f[NH];
        if (PHASE == 0) {
            // fused embed: h = elu(elu(x@We1+be1)@We2+be2)
            float4 xv = reinterpret_cast<const float4*>(x)[b*NP + r];
            float t[NH];
#pragma unroll
            for (int c = 0; c < NH; c++) {
                float a = __ldg(&be1[c]);
                a = fmaf(xv.x, __ldg(&We1[0*NH+c]), a);
                a = fmaf(xv.y, __ldg(&We1[1*NH+c]), a);
                a = fmaf(xv.z, __ldg(&We1[2*NH+c]), a);
                a = fmaf(xv.w, __ldg(&We1[3*NH+c]), a);
                t[c] = elu1(a);
            }
#pragma unroll
            for (int c = 0; c < NH; c++) {
                float a = __ldg(&be2[c]);
#pragma unroll
                for (int d = 0; d < NH; d++) a = fmaf(t[d], __ldg(&We2[d*NH+c]), a);
                f[c] = elu1(a);
            }
        } else {
            const float4* src = reinterpret_cast<const float4*>(g_f1 + ((size_t)b*NP + r)*NH);
            float4 v0=src[0], v1=src[1], v2=src[2], v3=src[3];
            f[0]=v0.x; f[1]=v0.y; f[2]=v0.z; f[3]=v0.w;
            f[4]=v1.x; f[5]=v1.y; f[6]=v1.z; f[7]=v1.w;
            f[8]=v2.x; f[9]=v2.y; f[10]=v2.z; f[11]=v2.w;
            f[12]=v3.x; f[13]=v3.y; f[14]=v3.z; f[15]=v3.w;
        }
#pragma unroll
        for (int d = 0; d < NH; d++) region[d*HTP + r] = f[d];
        float sA = 0.f, sB = 0.f;   // matches packed-dot half split -> exact self-0
#pragma unroll
        for (int d = 0; d < 8; d++)  sA = fmaf(f[d], f[d], sA);
#pragma unroll
        for (int d = 8; d < 16; d++) sB = fmaf(f[d], f[d], sB);
        sqsh[r] = sA + sB;
    }
    {   // W_c prep: transposed + xi/xj regroup
        int c = tid >> 4, d = tid & 15;
        float w1 = Wc[d*NH + c];
        float w2 = Wc[(NH+d)*NH + c];
        w2t[c*NH+d] = w2;
        wdt[c*NH+d] = w1 - w2;
    }
    if (tid < NH) bcs[tid] = bc[tid];
    __syncthreads();

    int i = ((blockIdx.x & 1) << 8) + tid;
    float hir[NH];
#pragma unroll
    for (int d = 0; d < NH; d++) hir[d] = region[d*HTP + i];
    float sqi = sqsh[i];
    ull hi2[NH];
#pragma unroll
    for (int d = 0; d < NH; d++) hi2[d] = pack2(hir[d], hir[d]);
    ull sqi2p1 = pack2(sqi + 1.f, sqi + 1.f);   // +1 bias folded in (no clamp)
    ull neg2   = pack2(-2.f, -2.f);

    // ---- top-8 smallest d2: f32x2 dots + batched sort-merge selection ----
    unsigned nd[NK];
#pragma unroll
    for (int k = 0; k < NK; k++) nd[k] = 0xFFFFFFFFu;

#pragma unroll 1
    for (int j = 0; j < NP; j += 8) {
        ull accA[4], accB[4];
#pragma unroll
        for (int p = 0; p < 4; p++) { accA[p] = 0ull; accB[p] = 0ull; }
#pragma unroll
        for (int d = 0; d < 8; d++) {
            ulonglong2 v01 = *reinterpret_cast<const ulonglong2*>(&region[d*HTP + j]);
            ulonglong2 v23 = *reinterpret_cast<const ulonglong2*>(&region[d*HTP + j + 4]);
            accA[0] = fma2(hi2[d], v01.x, accA[0]);
            accA[1] = fma2(hi2[d], v01.y, accA[1]);
            accA[2] = fma2(hi2[d], v23.x, accA[2]);
            accA[3] = fma2(hi2[d], v23.y, accA[3]);
        }
#pragma unroll
        for (int d = 8; d < 16; d++) {
            ulonglong2 v01 = *reinterpret_cast<const ulonglong2*>(&region[d*HTP + j]);
            ulonglong2 v23 = *reinterpret_cast<const ulonglong2*>(&region[d*HTP + j + 4]);
            accB[0] = fma2(hi2[d], v01.x, accB[0]);
            accB[1] = fma2(hi2[d], v01.y, accB[1]);
            accB[2] = fma2(hi2[d], v23.x, accB[2]);
            accB[3] = fma2(hi2[d], v23.y, accB[3]);
        }
        ulonglong2 s01 = *reinterpret_cast<const ulonglong2*>(&sqsh[j]);
        ulonglong2 s23 = *reinterpret_cast<const ulonglong2*>(&sqsh[j + 4]);
        ull sq4[4]; sq4[0]=s01.x; sq4[1]=s01.y; sq4[2]=s23.x; sq4[3]=s23.y;
        unsigned kk[8];
#pragma unroll
        for (int p = 0; p < 4; p++) {
            ull dot  = add2(accA[p], accB[p]);
            ull d2p1 = fma2(neg2, dot, add2(sqi2p1, sq4[p]));   // d2 + 1
            float2 pr = unpack2(d2p1);
            kk[2*p+0] = packkey(pr.x, j + 2*p);
            kk[2*p+1] = packkey(pr.y, j + 2*p + 1);
        }
        sort8(kk);
        mergeTop8(nd, kk);
    }

    // base_i = bc + hi @ (W1 - W2)
    float base[NH];
#pragma unroll
    for (int c = 0; c < NH; c++) {
        float a = bcs[c];
#pragma unroll
        for (int d = 0; d < NH; d++) a = fmaf(hir[d], wdt[c*NH+d], a);
        base[c] = a;
    }

    // ---- y_r = h_r @ W2 into registers, then overwrite region (pitch YP) ----
    float yrows[2][NH];
#pragma unroll
    for (int t2 = 0; t2 < 2; t2++) {
        int r = tid + t2*256;
        float f[NH];
#pragma unroll
        for (int d = 0; d < NH; d++) f[d] = region[d*HTP + r];
#pragma unroll
        for (int c = 0; c < NH; c++) {
            float a = 0.f;
#pragma unroll
            for (int d = 0; d < NH; d++) a = fmaf(f[d], w2t[c*NH+d], a);
            yrows[t2][c] = a;
        }
    }
    __syncthreads();   // all hT reads complete
#pragma unroll
    for (int t2 = 0; t2 < 2; t2++) {
        int r = tid + t2*256;
#pragma unroll
        for (int c = 0; c < NH; c++) region[r*YP + c] = yrows[t2][c];
    }
    __syncthreads();

    // ---- gather: m = base_i + y_j ; max over 8 edges; single elu ----
    float acc[NH];
#pragma unroll
    for (int c = 0; c < NH; c++) acc[c] = -3.4e38f;
#pragma unroll
    for (int e = 0; e < NK; e++) {
        int j = nd[e] & 511u;
        const float4* yp = reinterpret_cast<const float4*>(&region[j*YP]);
        float4 b0 = yp[0], b1 = yp[1], b2 = yp[2], b3 = yp[3];
        float yv[NH];
        yv[0]=b0.x; yv[1]=b0.y; yv[2]=b0.z; yv[3]=b0.w;
        yv[4]=b1.x; yv[5]=b1.y; yv[6]=b1.z; yv[7]=b1.w;
        yv[8]=b2.x; yv[9]=b2.y; yv[10]=b2.z; yv[11]=b2.w;
        yv[12]=b3.x; yv[13]=b3.y; yv[14]=b3.z; yv[15]=b3.w;
#pragma unroll
        for (int c = 0; c < NH; c++) acc[c] = fmaxf(acc[c], base[c] + yv[c]);
    }

    float op[NH];
#pragma unroll
    for (int c = 0; c < NH; c++) op[c] = elu1(acc[c]);   // elu(max) == max(elu)

    if (PHASE == 0) {
        float4* dst = reinterpret_cast<float4*>(g_f1 + ((size_t)b*NP + i)*NH);
        dst[0] = make_float4(op[0],op[1],op[2],op[3]);
        dst[1] = make_float4(op[4],op[5],op[6],op[7]);
        dst[2] = make_float4(op[8],op[9],op[10],op[11]);
        dst[3] = make_float4(op[12],op[13],op[14],op[15]);
    } else {
        // fused mean-pool: block-level channel sums -> g_pool[blockIdx.x][16]
        __syncthreads();   // gather reads of region done
#pragma unroll
        for (int c = 0; c < NH; c++) region[tid*RP + c] = op[c];
        __syncthreads();
        int c = tid & 15, part = tid >> 4;
        float s = 0.f;
#pragma unroll
        for (int k = 0; k < 16; k++) s += region[(part + k*16)*RP + c];
        sqsh[tid] = s;
        __syncthreads();
        if (tid < NH) {
            float t = 0.f;
#pragma unroll
            for (int k = 0; k < 16; k++) t += sqsh[k*16 + tid];
            g_pool[blockIdx.x*NH + tid] = t;
        }
    }
}

// ------------------------------------------------------------ head ----
__global__ void __launch_bounds__(256) k_head(
    const float* __restrict__ Wo1, const float* __restrict__ bo1,
    const float* __restrict__ Wo2, const float* __restrict__ bo2,
    const float* __restrict__ Wo3, const float* __restrict__ bo3,
    float* __restrict__ out, int out_size)
{
    int b = threadIdx.x;
    const float* gp = g_pool + b*2*NH;
    float p[NH];
#pragma unroll
    for (int c = 0; c < NH; c++) p[c] = (gp[c] + gp[NH + c]) * (1.0f/NP);
    float t1[8];
#pragma unroll
    for (int cc = 0; cc < 8; cc++) {
        float a = __ldg(&bo1[cc]);
#pragma unroll
        for (int d = 0; d < 16; d++) a = fmaf(p[d], __ldg(&Wo1[d*8+cc]), a);
        t1[cc] = elu1(a);
    }
    float t2[4];
#pragma unroll
    for (int cc = 0; cc < 4; cc++) {
        float a = __ldg(&bo2[cc]);
#pragma unroll
        for (int d = 0; d < 8; d++) a = fmaf(t1[d], __ldg(&Wo2[d*4+cc]), a);
        t2[cc] = elu1(a);
    }
    float o = __ldg(&bo3[0]);
#pragma unroll
    for (int d = 0; d < 4; d++) o = fmaf(t2[d], __ldg(&Wo3[d]), o);
    out[b] = o;
    if (out_size >= 2*NB) out[NB + b] = (float)b;   // pooled_batch = arange(B)
}

// --------------------------------------------------------------- launch ----
extern "C" void kernel_launch(void* const* d_in, const int* in_sizes, int n_in,
                              void* d_out, int out_size)
{
    int wb = n_in - 12;
    const float* x   = (const float*)d_in[0];
    const float* We1 = (const float*)d_in[wb+0];
    const float* be1 = (const float*)d_in[wb+1];
    const float* We2 = (const float*)d_in[wb+2];
    const float* be2 = (const float*)d_in[wb+3];
    const float* Wc  = (const float*)d_in[wb+4];
    const float* bcp = (const float*)d_in[wb+5];
    const float* Wo1 = (const float*)d_in[wb+6];
    const float* bo1 = (const float*)d_in[wb+7];
    const float* Wo2 = (const float*)d_in[wb+8];
    const float* bo2 = (const float*)d_in[wb+9];
    const float* Wo3 = (const float*)d_in[wb+10];
    const float* bo3 = (const float*)d_in[wb+11];

    k_edgeconv<0><<<NB*2, 256>>>(x, We1, be1, We2, be2, Wc, bcp);
    k_edgeconv<1><<<NB*2, 256>>>(x, We1, be1, We2, be2, Wc, bcp);
    k_head<<<1, 256>>>(Wo1, bo1, Wo2, bo2, Wo3, bo3, (float*)d_out, out_size);
}

// round 7
// speedup vs baseline: 4.0555x; 1.1487x over previous
#include <cuda_runtime.h>

#define NB 256
#define NP 512
#define NH 16
#define NK 8
#define NPTS (NB*NP)
#define HTP 520           // transposed pitch (floats); 2080B rows, 16B-aligned
#define YP  20            // y-row pitch (floats), bank-spread for gather
#define RP  17            // pool-reduce row pitch

typedef unsigned long long ull;

__device__ float g_f1  [NPTS*NH];
__device__ float g_pool[NB*NH];   // per-graph channel sums

__device__ __forceinline__ float elu1(float x) {
    return x > 0.f ? x : (__expf(x) - 1.f);
}

// ---- f32x2 packed helpers ----
__device__ __forceinline__ ull fma2(ull a, ull b, ull c) {
    ull d; asm("fma.rn.f32x2 %0, %1, %2, %3;" : "=l"(d) : "l"(a), "l"(b), "l"(c)); return d;
}
__device__ __forceinline__ ull add2(ull a, ull b) {
    ull d; asm("add.rn.f32x2 %0, %1, %2;" : "=l"(d) : "l"(a), "l"(b)); return d;
}
__device__ __forceinline__ ull pack2(float lo, float hi) {
    ull d; asm("mov.b64 %0, {%1, %2};" : "=l"(d) : "f"(lo), "f"(hi)); return d;
}
__device__ __forceinline__ float2 unpack2(ull v) {
    float lo, hi; asm("mov.b64 {%0, %1}, %2;" : "=f"(lo), "=f"(hi) : "l"(v));
    return make_float2(lo, hi);
}

// key = bits(d2 + 1.0), low 9 bits = j. d2+1 >= ~1 (positive normal) -> uint order ok.
__device__ __forceinline__ unsigned packkey(float d2p1, int j) {
    return (__float_as_uint(d2p1) & 0xFFFFFE00u) | (unsigned)j;
}

#define CE(x, y) { unsigned _lo = umin(x, y); y = umax(x, y); x = _lo; }

// Sort 4 keys ascending (5 CE).
__device__ __forceinline__ void sort4(unsigned (&k)[4]) {
    CE(k[0],k[1]); CE(k[2],k[3]);
    CE(k[0],k[2]); CE(k[1],k[3]);
    CE(k[1],k[2]);
}

// nd (asc 8) <- 8 smallest of nd ∪ k (k asc 4). Pad-merge + bitonic clean-up.
__device__ __forceinline__ void merge4(unsigned (&nd)[NK], const unsigned (&k)[4]) {
    unsigned L[8];
    L[0]=nd[0]; L[1]=nd[1]; L[2]=nd[2]; L[3]=nd[3];
    L[4]=umin(nd[4],k[3]); L[5]=umin(nd[5],k[2]);
    L[6]=umin(nd[6],k[1]); L[7]=umin(nd[7],k[0]);
    CE(L[0],L[4]); CE(L[1],L[5]); CE(L[2],L[6]); CE(L[3],L[7]);
    CE(L[0],L[2]); CE(L[1],L[3]); CE(L[4],L[6]); CE(L[5],L[7]);
    CE(L[0],L[1]); CE(L[2],L[3]); CE(L[4],L[5]); CE(L[6],L[7]);
#pragma unroll
    for (int i = 0; i < 8; i++) nd[i] = L[i];
}

// ------------------------------------------------------------- edgeconv ----
// One CTA = one graph (512 points); each thread owns rows tid and tid+256.
// PHASE 0: embed(x) -> conv -> g_f1      (embed fused in prologue)
// PHASE 1: g_f1 -> conv -> g_pool sums   (pool fused in epilogue)
template<int PHASE>
__global__ void __launch_bounds__(256, 2) k_edgeconv(
    const float* __restrict__ x,
    const float* __restrict__ We1, const float* __restrict__ be1,
    const float* __restrict__ We2, const float* __restrict__ be2,
    const float* __restrict__ Wc,  const float* __restrict__ bc)
{
    __shared__ __align__(16) float region[NP*YP];    // hT -> y -> pool scratch
    __shared__ __align__(16) float sqsh[NP];
    __shared__ float w2t[NH*NH];   // [c][d] = Wc[(16+d)*16+c]
    __shared__ float wdt[NH*NH];   // [c][d] = Wc[d*16+c] - w2
    __shared__ float bcs[NH];

    int tid = threadIdx.x;
    int b   = blockIdx.x;

    // ---- prologue: h rows (transposed) + squared norms (single fp32 chain) ----
#pragma unroll
    for (int t2 = 0; t2 < 2; t2++) {
        int r = tid + t2*256;
        float f[NH];
        if (PHASE == 0) {
            float4 xv = reinterpret_cast<const float4*>(x)[b*NP + r];
            float t[NH];
#pragma unroll
            for (int c = 0; c < NH; c++) {
                float a = __ldg(&be1[c]);
                a = fmaf(xv.x, __ldg(&We1[0*NH+c]), a);
                a = fmaf(xv.y, __ldg(&We1[1*NH+c]), a);
                a = fmaf(xv.z, __ldg(&We1[2*NH+c]), a);
                a = fmaf(xv.w, __ldg(&We1[3*NH+c]), a);
                t[c] = elu1(a);
            }
#pragma unroll
            for (int c = 0; c < NH; c++) {
                float a = __ldg(&be2[c]);
#pragma unroll
                for (int d = 0; d < NH; d++) a = fmaf(t[d], __ldg(&We2[d*NH+c]), a);
                f[c] = elu1(a);
            }
        } else {
            const float4* src = reinterpret_cast<const float4*>(g_f1 + ((size_t)b*NP + r)*NH);
            float4 v0=src[0], v1=src[1], v2=src[2], v3=src[3];
            f[0]=v0.x; f[1]=v0.y; f[2]=v0.z; f[3]=v0.w;
            f[4]=v1.x; f[5]=v1.y; f[6]=v1.z; f[7]=v1.w;
            f[8]=v2.x; f[9]=v2.y; f[10]=v2.z; f[11]=v2.w;
            f[12]=v3.x; f[13]=v3.y; f[14]=v3.z; f[15]=v3.w;
        }
#pragma unroll
        for (int d = 0; d < NH; d++) region[d*HTP + r] = f[d];
        float s = 0.f;          // SAME single chain as the packed dot -> exact self-0
#pragma unroll
        for (int d = 0; d < NH; d++) s = fmaf(f[d], f[d], s);
        sqsh[r] = s;
    }
    {   // W_c prep: transposed + xi/xj regroup
        int c = tid >> 4, d = tid & 15;
        float w1 = Wc[d*NH + c];
        float w2 = Wc[(NH+d)*NH + c];
        w2t[c*NH+d] = w2;
        wdt[c*NH+d] = w1 - w2;
    }
    if (tid < NH) bcs[tid] = bc[tid];
    __syncthreads();

    // ---- per-thread i rows: i0 = tid, i1 = tid + 256 ----
    ull hiA[NH], hiB[NH];
#pragma unroll
    for (int d = 0; d < NH; d++) {
        float a = region[d*HTP + tid];
        float c = region[d*HTP + tid + 256];
        hiA[d] = pack2(a, a);
        hiB[d] = pack2(c, c);
    }
    ull sqA2p1 = pack2(sqsh[tid] + 1.f,       sqsh[tid] + 1.f);
    ull sqB2p1 = pack2(sqsh[tid + 256] + 1.f, sqsh[tid + 256] + 1.f);
    ull neg2   = pack2(-2.f, -2.f);

    unsigned ndA[NK], ndB[NK];
#pragma unroll
    for (int k = 0; k < NK; k++) { ndA[k] = 0xFFFFFFFFu; ndB[k] = 0xFFFFFFFFu; }

#pragma unroll 1
    for (int j = 0; j < NP; j += 4) {
        ull a0 = 0ull, a1 = 0ull, b0 = 0ull, b1 = 0ull;
#pragma unroll
        for (int d = 0; d < NH; d++) {
            ulonglong2 v = *reinterpret_cast<const ulonglong2*>(&region[d*HTP + j]);
            a0 = fma2(hiA[d], v.x, a0);
            a1 = fma2(hiA[d], v.y, a1);
            b0 = fma2(hiB[d], v.x, b0);
            b1 = fma2(hiB[d], v.y, b1);
        }
        ulonglong2 sj = *reinterpret_cast<const ulonglong2*>(&sqsh[j]);
        {
            ull d01 = fma2(neg2, a0, add2(sqA2p1, sj.x));
            ull d23 = fma2(neg2, a1, add2(sqA2p1, sj.y));
            float2 p01 = unpack2(d01), p23 = unpack2(d23);
            unsigned kk[4];
            kk[0] = packkey(p01.x, j);   kk[1] = packkey(p01.y, j+1);
            kk[2] = packkey(p23.x, j+2); kk[3] = packkey(p23.y, j+3);
            sort4(kk); merge4(ndA, kk);
        }
        {
            ull d01 = fma2(neg2, b0, add2(sqB2p1, sj.x));
            ull d23 = fma2(neg2, b1, add2(sqB2p1, sj.y));
            float2 p01 = unpack2(d01), p23 = unpack2(d23);
            unsigned kk[4];
            kk[0] = packkey(p01.x, j);   kk[1] = packkey(p01.y, j+1);
            kk[2] = packkey(p23.x, j+2); kk[3] = packkey(p23.y, j+3);
            sort4(kk); merge4(ndB, kk);
        }
    }

    // ---- base + y for both rows (hT still live), then swap region to y ----
    float base[2][NH], yrow[2][NH];
#pragma unroll
    for (int t2 = 0; t2 < 2; t2++) {
        int r = tid + t2*256;
        float f[NH];
#pragma unroll
        for (int d = 0; d < NH; d++) f[d] = region[d*HTP + r];
#pragma unroll
        for (int c = 0; c < NH; c++) {
            float a = bcs[c];
            float y = 0.f;
#pragma unroll
            for (int d = 0; d < NH; d++) {
                a = fmaf(f[d], wdt[c*NH+d], a);
                y = fmaf(f[d], w2t[c*NH+d], y);
            }
            base[t2][c] = a;
            yrow[t2][c] = y;
        }
    }
    __syncthreads();   // all hT reads complete
#pragma unroll
    for (int t2 = 0; t2 < 2; t2++) {
        int r = tid + t2*256;
#pragma unroll
        for (int c = 0; c < NH; c++) region[r*YP + c] = yrow[t2][c];
    }
    __syncthreads();

    // ---- gather: m = base_i + y_j ; max over 8 edges; single elu ----
    float op[2][NH];
#pragma unroll
    for (int t2 = 0; t2 < 2; t2++) {
        const unsigned* nd = (t2 == 0) ? ndA : ndB;
        float acc[NH];
#pragma unroll
        for (int c = 0; c < NH; c++) acc[c] = -3.4e38f;
#pragma unroll
        for (int e = 0; e < NK; e++) {
            int j = nd[e] & 511u;
            const float4* yp = reinterpret_cast<const float4*>(&region[j*YP]);
            float4 v0 = yp[0], v1 = yp[1], v2 = yp[2], v3 = yp[3];
            float yv[NH];
            yv[0]=v0.x; yv[1]=v0.y; yv[2]=v0.z; yv[3]=v0.w;
            yv[4]=v1.x; yv[5]=v1.y; yv[6]=v1.z; yv[7]=v1.w;
            yv[8]=v2.x; yv[9]=v2.y; yv[10]=v2.z; yv[11]=v2.w;
            yv[12]=v3.x; yv[13]=v3.y; yv[14]=v3.z; yv[15]=v3.w;
#pragma unroll
            for (int c = 0; c < NH; c++) acc[c] = fmaxf(acc[c], base[t2][c] + yv[c]);
        }
#pragma unroll
        for (int c = 0; c < NH; c++) op[t2][c] = elu1(acc[c]);  // elu(max)==max(elu)
    }

    if (PHASE == 0) {
#pragma unroll
        for (int t2 = 0; t2 < 2; t2++) {
            int r = tid + t2*256;
            float4* dst = reinterpret_cast<float4*>(g_f1 + ((size_t)b*NP + r)*NH);
            dst[0] = make_float4(op[t2][0],op[t2][1],op[t2][2],op[t2][3]);
            dst[1] = make_float4(op[t2][4],op[t2][5],op[t2][6],op[t2][7]);
            dst[2] = make_float4(op[t2][8],op[t2][9],op[t2][10],op[t2][11]);
            dst[3] = make_float4(op[t2][12],op[t2][13],op[t2][14],op[t2][15]);
        }
    } else {
        // fused mean-pool: whole-graph channel sums -> g_pool[b][16]
        __syncthreads();   // gather reads of region done
#pragma unroll
        for (int c = 0; c < NH; c++) region[tid*RP + c] = op[0][c] + op[1][c];
        __syncthreads();
        int c = tid & 15, part = tid >> 4;
        float s = 0.f;
#pragma unroll
        for (int k = 0; k < 16; k++) s += region[(part + k*16)*RP + c];
        sqsh[tid] = s;
        __syncthreads();
        if (tid < NH) {
            float t = 0.f;
#pragma unroll
            for (int k = 0; k < 16; k++) t += sqsh[k*16 + tid];
            g_pool[b*NH + tid] = t;
        }
    }
}

// ------------------------------------------------------------ head ----
__global__ void __launch_bounds__(256) k_head(
    const float* __restrict__ Wo1, const float* __restrict__ bo1,
    const float* __restrict__ Wo2, const float* __restrict__ bo2,
    const float* __restrict__ Wo3, const float* __restrict__ bo3,
    float* __restrict__ out, int out_size)
{
    int b = threadIdx.x;
    const float* gp = g_pool + b*NH;
    float p[NH];
#pragma unroll
    for (int c = 0; c < NH; c++) p[c] = gp[c] * (1.0f/NP);
    float t1[8];
#pragma unroll
    for (int cc = 0; cc < 8; cc++) {
        float a = __ldg(&bo1[cc]);
#pragma unroll
        for (int d = 0; d < 16; d++) a = fmaf(p[d], __ldg(&Wo1[d*8+cc]), a);
        t1[cc] = elu1(a);
    }
    float t2[4];
#pragma unroll
    for (int cc = 0; cc < 4; cc++) {
        float a = __ldg(&bo2[cc]);
#pragma unroll
        for (int d = 0; d < 8; d++) a = fmaf(t1[d], __ldg(&Wo2[d*4+cc]), a);
        t2[cc] = elu1(a);
    }
    float o = __ldg(&bo3[0]);
#pragma unroll
    for (int d = 0; d < 4; d++) o = fmaf(t2[d], __ldg(&Wo3[d]), o);
    out[b] = o;
    if (out_size >= 2*NB) out[NB + b] = (float)b;   // pooled_batch = arange(B)
}

// --------------------------------------------------------------- launch ----
extern "C" void kernel_launch(void* const* d_in, const int* in_sizes, int n_in,
                              void* d_out, int out_size)
{
    int wb = n_in - 12;
    const float* x   = (const float*)d_in[0];
    const float* We1 = (const float*)d_in[wb+0];
    const float* be1 = (const float*)d_in[wb+1];
    const float* We2 = (const float*)d_in[wb+2];
    const float* be2 = (const float*)d_in[wb+3];
    const float* Wc  = (const float*)d_in[wb+4];
    const float* bcp = (const float*)d_in[wb+5];
    const float* Wo1 = (const float*)d_in[wb+6];
    const float* bo1 = (const float*)d_in[wb+7];
    const float* Wo2 = (const float*)d_in[wb+8];
    const float* bo2 = (const float*)d_in[wb+9];
    const float* Wo3 = (const float*)d_in[wb+10];
    const float* bo3 = (const float*)d_in[wb+11];

    k_edgeconv<0><<<NB, 256>>>(x, We1, be1, We2, be2, Wc, bcp);
    k_edgeconv<1><<<NB, 256>>>(x, We1, be1, We2, be2, Wc, bcp);
    k_head<<<1, 256>>>(Wo1, bo1, Wo2, bo2, Wo3, bo3, (float*)d_out, out_size);
}

// round 8
// speedup vs baseline: 4.3385x; 1.0698x over previous
#include <cuda_runtime.h>

#define NB 256
#define NP 512
#define NH 16
#define NK 8
#define NPTS (NB*NP)
#define HTP 520           // transposed pitch (floats); 2080B rows, 16B-aligned
#define YP  20            // y-row pitch (floats), bank-spread for gather
#define RP  17            // pool-reduce row pitch

typedef unsigned long long ull;

__device__ float g_pool[NB*NH];   // per-graph channel sums

__device__ __forceinline__ float elu1(float x) {
    return x > 0.f ? x : (__expf(x) - 1.f);
}

// ---- f32x2 packed helpers ----
__device__ __forceinline__ ull fma2(ull a, ull b, ull c) {
    ull d; asm("fma.rn.f32x2 %0, %1, %2, %3;" : "=l"(d) : "l"(a), "l"(b), "l"(c)); return d;
}
__device__ __forceinline__ ull add2(ull a, ull b) {
    ull d; asm("add.rn.f32x2 %0, %1, %2;" : "=l"(d) : "l"(a), "l"(b)); return d;
}
__device__ __forceinline__ ull pack2(float lo, float hi) {
    ull d; asm("mov.b64 %0, {%1, %2};" : "=l"(d) : "f"(lo), "f"(hi)); return d;
}
__device__ __forceinline__ float2 unpack2(ull v) {
    float lo, hi; asm("mov.b64 {%0, %1}, %2;" : "=f"(lo), "=f"(hi) : "l"(v));
    return make_float2(lo, hi);
}

// key = bits(d2 + 1.0), low 9 bits = j. d2+1 >= ~1 (positive normal) -> uint order ok.
__device__ __forceinline__ unsigned packkey(float d2p1, int j) {
    return (__float_as_uint(d2p1) & 0xFFFFFE00u) | (unsigned)j;
}

#define CE(x, y) { unsigned _lo = umin(x, y); y = umax(x, y); x = _lo; }

// Optimal 19-CE sorting network for 8 keys (ascending).
__device__ __forceinline__ void sort8(unsigned (&k)[8]) {
    CE(k[0],k[1]); CE(k[2],k[3]); CE(k[4],k[5]); CE(k[6],k[7]);
    CE(k[0],k[2]); CE(k[1],k[3]); CE(k[4],k[6]); CE(k[5],k[7]);
    CE(k[1],k[2]); CE(k[5],k[6]); CE(k[0],k[4]); CE(k[3],k[7]);
    CE(k[1],k[5]); CE(k[2],k[6]);
    CE(k[1],k[4]); CE(k[3],k[6]);
    CE(k[2],k[4]); CE(k[3],k[5]);
    CE(k[3],k[4]);
}

// nd (asc) <- 8 smallest of nd ∪ k (k asc 8). min-pair (bitonic) + clean-up.
__device__ __forceinline__ void mergeTop8(unsigned (&nd)[NK], const unsigned (&k)[8]) {
    unsigned L[8];
#pragma unroll
    for (int i = 0; i < 8; i++) L[i] = umin(nd[i], k[7-i]);
    CE(L[0],L[4]); CE(L[1],L[5]); CE(L[2],L[6]); CE(L[3],L[7]);
    CE(L[0],L[2]); CE(L[1],L[3]); CE(L[4],L[6]); CE(L[5],L[7]);
    CE(L[0],L[1]); CE(L[2],L[3]); CE(L[4],L[5]); CE(L[6],L[7]);
#pragma unroll
    for (int i = 0; i < 8; i++) nd[i] = L[i];
}

// --------------------------------------------------------------- conv ------
// One edgeconv pass. Assumes region holds hT (pitch HTP) and sqsh the norms.
// Produces op[2][16] = conv output rows (tid, tid+256). Leaves region holding
// y rows (pitch YP). Contains 2 internal barriers.
__device__ __forceinline__ void conv_pass(
    float* region, float* sqsh,
    const float* w2t, const float* wdt, const float* bcs,
    int tid, float (&op)[2][NH])
{
    ull hiA[NH], hiB[NH];
#pragma unroll
    for (int d = 0; d < NH; d++) {
        float a = region[d*HTP + tid];
        float c = region[d*HTP + tid + 256];
        hiA[d] = pack2(a, a);
        hiB[d] = pack2(c, c);
    }
    ull sqA2p1 = pack2(sqsh[tid] + 1.f,       sqsh[tid] + 1.f);
    ull sqB2p1 = pack2(sqsh[tid + 256] + 1.f, sqsh[tid + 256] + 1.f);
    ull neg2   = pack2(-2.f, -2.f);

    unsigned ndA[NK], ndB[NK];
#pragma unroll
    for (int k = 0; k < NK; k++) { ndA[k] = 0xFFFFFFFFu; ndB[k] = 0xFFFFFFFFu; }

#pragma unroll 1
    for (int j = 0; j < NP; j += 8) {
        unsigned kkA[8], kkB[8];
#pragma unroll
        for (int s = 0; s < 2; s++) {
            int jj = j + s*4;
            ull a0 = 0ull, a1 = 0ull, b0 = 0ull, b1 = 0ull;
#pragma unroll
            for (int d = 0; d < NH; d++) {
                ulonglong2 v = *reinterpret_cast<const ulonglong2*>(&region[d*HTP + jj]);
                a0 = fma2(hiA[d], v.x, a0);
                a1 = fma2(hiA[d], v.y, a1);
                b0 = fma2(hiB[d], v.x, b0);
                b1 = fma2(hiB[d], v.y, b1);
            }
            ulonglong2 sj = *reinterpret_cast<const ulonglong2*>(&sqsh[jj]);
            {
                ull d01 = fma2(neg2, a0, add2(sqA2p1, sj.x));
                ull d23 = fma2(neg2, a1, add2(sqA2p1, sj.y));
                float2 p01 = unpack2(d01), p23 = unpack2(d23);
                kkA[s*4+0] = packkey(p01.x, jj);   kkA[s*4+1] = packkey(p01.y, jj+1);
                kkA[s*4+2] = packkey(p23.x, jj+2); kkA[s*4+3] = packkey(p23.y, jj+3);
            }
            {
                ull d01 = fma2(neg2, b0, add2(sqB2p1, sj.x));
                ull d23 = fma2(neg2, b1, add2(sqB2p1, sj.y));
                float2 p01 = unpack2(d01), p23 = unpack2(d23);
                kkB[s*4+0] = packkey(p01.x, jj);   kkB[s*4+1] = packkey(p01.y, jj+1);
                kkB[s*4+2] = packkey(p23.x, jj+2); kkB[s*4+3] = packkey(p23.y, jj+3);
            }
        }
        sort8(kkA); mergeTop8(ndA, kkA);
        sort8(kkB); mergeTop8(ndB, kkB);
    }

    // ---- base + y for both rows (hT still live), then swap region to y ----
    float base[2][NH], yrow[2][NH];
#pragma unroll
    for (int t2 = 0; t2 < 2; t2++) {
        int r = tid + t2*256;
        float f[NH];
#pragma unroll
        for (int d = 0; d < NH; d++) f[d] = region[d*HTP + r];
#pragma unroll
        for (int c = 0; c < NH; c++) {
            float a = bcs[c];
            float y = 0.f;
#pragma unroll
            for (int d = 0; d < NH; d++) {
                a = fmaf(f[d], wdt[c*NH+d], a);
                y = fmaf(f[d], w2t[c*NH+d], y);
            }
            base[t2][c] = a;
            yrow[t2][c] = y;
        }
    }
    __syncthreads();   // all hT reads complete
#pragma unroll
    for (int t2 = 0; t2 < 2; t2++) {
        int r = tid + t2*256;
#pragma unroll
        for (int c = 0; c < NH; c++) region[r*YP + c] = yrow[t2][c];
    }
    __syncthreads();

    // ---- gather: m = base_i + y_j ; max over 8 edges; single elu ----
#pragma unroll
    for (int t2 = 0; t2 < 2; t2++) {
        const unsigned* nd = (t2 == 0) ? ndA : ndB;
        float acc[NH];
#pragma unroll
        for (int c = 0; c < NH; c++) acc[c] = -3.4e38f;
#pragma unroll
        for (int e = 0; e < NK; e++) {
            int j = nd[e] & 511u;
            const float4* yp = reinterpret_cast<const float4*>(&region[j*YP]);
            float4 v0 = yp[0], v1 = yp[1], v2 = yp[2], v3 = yp[3];
            float yv[NH];
            yv[0]=v0.x; yv[1]=v0.y; yv[2]=v0.z; yv[3]=v0.w;
            yv[4]=v1.x; yv[5]=v1.y; yv[6]=v1.z; yv[7]=v1.w;
            yv[8]=v2.x; yv[9]=v2.y; yv[10]=v2.z; yv[11]=v2.w;
            yv[12]=v3.x; yv[13]=v3.y; yv[14]=v3.z; yv[15]=v3.w;
#pragma unroll
            for (int c = 0; c < NH; c++) acc[c] = fmaxf(acc[c], base[t2][c] + yv[c]);
        }
#pragma unroll
        for (int c = 0; c < NH; c++) op[t2][c] = elu1(acc[c]);  // elu(max)==max(elu)
    }
}

// ------------------------------------------------------------- fused -------
// One CTA = one graph: embed -> conv0 -> conv1 -> pool, all in shared memory.
__global__ void __launch_bounds__(256, 2) k_fused(
    const float* __restrict__ x,
    const float* __restrict__ We1, const float* __restrict__ be1,
    const float* __restrict__ We2, const float* __restrict__ be2,
    const float* __restrict__ Wc,  const float* __restrict__ bc)
{
    __shared__ __align__(16) float region[NP*YP];    // hT -> y -> hT -> y -> pool
    __shared__ __align__(16) float sqsh[NP];
    __shared__ float w2t[NH*NH];   // [c][d] = Wc[(16+d)*16+c]
    __shared__ float wdt[NH*NH];   // [c][d] = Wc[d*16+c] - w2
    __shared__ float bcs[NH];

    int tid = threadIdx.x;
    int b   = blockIdx.x;

    // ---- prologue: fused embed -> hT + norms (single fp32 chain == dot) ----
#pragma unroll
    for (int t2 = 0; t2 < 2; t2++) {
        int r = tid + t2*256;
        float4 xv = reinterpret_cast<const float4*>(x)[b*NP + r];
        float t[NH], f[NH];
#pragma unroll
        for (int c = 0; c < NH; c++) {
            float a = __ldg(&be1[c]);
            a = fmaf(xv.x, __ldg(&We1[0*NH+c]), a);
            a = fmaf(xv.y, __ldg(&We1[1*NH+c]), a);
            a = fmaf(xv.z, __ldg(&We1[2*NH+c]), a);
            a = fmaf(xv.w, __ldg(&We1[3*NH+c]), a);
            t[c] = elu1(a);
        }
#pragma unroll
        for (int c = 0; c < NH; c++) {
            float a = __ldg(&be2[c]);
#pragma unroll
            for (int d = 0; d < NH; d++) a = fmaf(t[d], __ldg(&We2[d*NH+c]), a);
            f[c] = elu1(a);
        }
#pragma unroll
        for (int d = 0; d < NH; d++) region[d*HTP + r] = f[d];
        float s = 0.f;
#pragma unroll
        for (int d = 0; d < NH; d++) s = fmaf(f[d], f[d], s);
        sqsh[r] = s;
    }
    {   // W_c prep: transposed + xi/xj regroup
        int c = tid >> 4, d = tid & 15;
        float w1 = Wc[d*NH + c];
        float w2 = Wc[(NH+d)*NH + c];
        w2t[c*NH+d] = w2;
        wdt[c*NH+d] = w1 - w2;
    }
    if (tid < NH) bcs[tid] = bc[tid];
    __syncthreads();

    float op[2][NH];
    conv_pass(region, sqsh, w2t, wdt, bcs, tid, op);   // conv0

    // ---- re-seed region with f1 (transposed) + norms ----
    __syncthreads();   // conv0 gather reads of region(y) complete
#pragma unroll
    for (int t2 = 0; t2 < 2; t2++) {
        int r = tid + t2*256;
#pragma unroll
        for (int d = 0; d < NH; d++) region[d*HTP + r] = op[t2][d];
        float s = 0.f;
#pragma unroll
        for (int d = 0; d < NH; d++) s = fmaf(op[t2][d], op[t2][d], s);
        sqsh[r] = s;
    }
    __syncthreads();

    conv_pass(region, sqsh, w2t, wdt, bcs, tid, op);   // conv1

    // ---- fused mean-pool: whole-graph channel sums -> g_pool[b][16] ----
    __syncthreads();   // conv1 gather reads of region done
#pragma unroll
    for (int c = 0; c < NH; c++) region[tid*RP + c] = op[0][c] + op[1][c];
    __syncthreads();
    int c = tid & 15, part = tid >> 4;
    float s = 0.f;
#pragma unroll
    for (int k = 0; k < 16; k++) s += region[(part + k*16)*RP + c];
    sqsh[tid] = s;
    __syncthreads();
    if (tid < NH) {
        float t = 0.f;
#pragma unroll
        for (int k = 0; k < 16; k++) t += sqsh[k*16 + tid];
        g_pool[b*NH + tid] = t;
    }
}

// ------------------------------------------------------------ head ----
__global__ void __launch_bounds__(256) k_head(
    const float* __restrict__ Wo1, const float* __restrict__ bo1,
    const float* __restrict__ Wo2, const float* __restrict__ bo2,
    const float* __restrict__ Wo3, const float* __restrict__ bo3,
    float* __restrict__ out, int out_size)
{
    int b = threadIdx.x;
    const float* gp = g_pool + b*NH;
    float p[NH];
#pragma unroll
    for (int c = 0; c < NH; c++) p[c] = gp[c] * (1.0f/NP);
    float t1[8];
#pragma unroll
    for (int cc = 0; cc < 8; cc++) {
        float a = __ldg(&bo1[cc]);
#pragma unroll
        for (int d = 0; d < 16; d++) a = fmaf(p[d], __ldg(&Wo1[d*8+cc]), a);
        t1[cc] = elu1(a);
    }
    float t2[4];
#pragma unroll
    for (int cc = 0; cc < 4; cc++) {
        float a = __ldg(&bo2[cc]);
#pragma unroll
        for (int d = 0; d < 8; d++) a = fmaf(t1[d], __ldg(&Wo2[d*4+cc]), a);
        t2[cc] = elu1(a);
    }
    float o = __ldg(&bo3[0]);
#pragma unroll
    for (int d = 0; d < 4; d++) o = fmaf(t2[d], __ldg(&Wo3[d]), o);
    out[b] = o;
    if (out_size >= 2*NB) out[NB + b] = (float)b;   // pooled_batch = arange(B)
}

// --------------------------------------------------------------- launch ----
extern "C" void kernel_launch(void* const* d_in, const int* in_sizes, int n_in,
                              void* d_out, int out_size)
{
    int wb = n_in - 12;
    const float* x   = (const float*)d_in[0];
    const float* We1 = (const float*)d_in[wb+0];
    const float* be1 = (const float*)d_in[wb+1];
    const float* We2 = (const float*)d_in[wb+2];
    const float* be2 = (const float*)d_in[wb+3];
    const float* Wc  = (const float*)d_in[wb+4];
    const float* bcp = (const float*)d_in[wb+5];
    const float* Wo1 = (const float*)d_in[wb+6];
    const float* bo1 = (const float*)d_in[wb+7];
    const float* Wo2 = (const float*)d_in[wb+8];
    const float* bo2 = (const float*)d_in[wb+9];
    const float* Wo3 = (const float*)d_in[wb+10];
    const float* bo3 = (const float*)d_in[wb+11];

    k_fused<<<NB, 256>>>(x, We1, be1, We2, be2, Wc, bcp);
    k_head<<<1, 256>>>(Wo1, bo1, Wo2, bo2, Wo3, bo3, (float*)d_out, out_size);
}